// round 11
// baseline (speedup 1.0000x reference)
#include <cuda_runtime.h>
#include <cuda_bf16.h>
#include <math_constants.h>
#include <cstdint>

// ---------------------------------------------------------------------------
// Problem constants
// ---------------------------------------------------------------------------
#define S    2048
#define D    2048
#define NQ   32
#define NKV  8
#define HD   64
#define DKV  (NKV * HD)    // 512
#define KVS  (2 * DKV)     // 1024: packed K|V row stride
#define DQKV (D + KVS)     // 3072: packed Q|K|V projection width

// ---------------------------------------------------------------------------
// Scratch (device globals: no allocation allowed)
// ---------------------------------------------------------------------------
__device__ float g_QKV[S * DQKV];    // 24 MB fp32 [ Q(2048) | K(512) | V(512) ]

__device__ __nv_bfloat16 g_Ahi[S * D], g_Alo[S * D];            // x hi/lo, then Q hi/lo
__device__ __nv_bfloat16 g_KVhi[S * KVS], g_KVlo[S * KVS];      // K|V hi/lo (post norm)
__device__ __nv_bfloat16 g_Ohi[S * D], g_Olo[S * D];            // attention out hi/lo
__device__ __nv_bfloat16 g_WqkvThi[DQKV * D], g_WqkvTlo[DQKV * D]; // [Wq;Wk;Wv]^T
__device__ __nv_bfloat16 g_WoThi[D * D], g_WoTlo[D * D];        // Wo^T

// ---------------------------------------------------------------------------
// PTX helpers (base ISA only)
// ---------------------------------------------------------------------------
__device__ __forceinline__ uint32_t smem_u32(const void* p) {
    uint32_t a;
    asm("{ .reg .u64 t; cvta.to.shared.u64 t, %1; cvt.u32.u64 %0, t; }" : "=r"(a) : "l"(p));
    return a;
}
__device__ __forceinline__ void cp_async16(uint32_t dst, const void* src) {
    asm volatile("cp.async.cg.shared.global [%0], [%1], 16;" :: "r"(dst), "l"(src));
}
__device__ __forceinline__ void cp_commit() {
    asm volatile("cp.async.commit_group;" ::: "memory");
}
__device__ __forceinline__ void cp_wait2() {
    asm volatile("cp.async.wait_group 2;" ::: "memory");
}
__device__ __forceinline__ void cp_wait1() {
    asm volatile("cp.async.wait_group 1;" ::: "memory");
}
__device__ __forceinline__ void cp_wait0() {
    asm volatile("cp.async.wait_group 0;" ::: "memory");
}
__device__ __forceinline__ void ldsm_x4(uint32_t* r, uint32_t addr) {
    asm volatile("ldmatrix.sync.aligned.m8n8.x4.shared.b16 {%0,%1,%2,%3}, [%4];"
                 : "=r"(r[0]), "=r"(r[1]), "=r"(r[2]), "=r"(r[3]) : "r"(addr));
}
__device__ __forceinline__ void ldsm_x4_t(uint32_t* r, uint32_t addr) {
    asm volatile("ldmatrix.sync.aligned.m8n8.x4.trans.shared.b16 {%0,%1,%2,%3}, [%4];"
                 : "=r"(r[0]), "=r"(r[1]), "=r"(r[2]), "=r"(r[3]) : "r"(addr));
}
__device__ __forceinline__ void mma16816(float* c, const uint32_t* a, const uint32_t* b) {
    asm volatile(
        "mma.sync.aligned.m16n8k16.row.col.f32.bf16.bf16.f32 "
        "{%0,%1,%2,%3}, {%4,%5,%6,%7}, {%8,%9}, {%0,%1,%2,%3};"
        : "+f"(c[0]), "+f"(c[1]), "+f"(c[2]), "+f"(c[3])
        : "r"(a[0]), "r"(a[1]), "r"(a[2]), "r"(a[3]), "r"(b[0]), "r"(b[1]));
}
__device__ __forceinline__ void pack2(float x, float y, uint32_t& hi, uint32_t& lo) {
    __nv_bfloat16 hx = __float2bfloat16(x), hy = __float2bfloat16(y);
    __nv_bfloat162 hh = __halves2bfloat162(hx, hy);
    hi = *reinterpret_cast<uint32_t*>(&hh);
    __nv_bfloat162 ll = __halves2bfloat162(__float2bfloat16(x - __bfloat162float(hx)),
                                           __float2bfloat16(y - __bfloat162float(hy)));
    lo = *reinterpret_cast<uint32_t*>(&ll);
}

// ---------------------------------------------------------------------------
// Split-fp32 conversion kernels (input x + weights)
// ---------------------------------------------------------------------------
__global__ void cvt_hilo(const float* __restrict__ src,
                         __nv_bfloat16* __restrict__ hi,
                         __nv_bfloat16* __restrict__ lo, int n)
{
    int i = (blockIdx.x * blockDim.x + threadIdx.x) * 4;
    if (i >= n) return;
    float4 v = *(const float4*)(src + i);
    __nv_bfloat16 h0 = __float2bfloat16(v.x), h1 = __float2bfloat16(v.y);
    __nv_bfloat16 h2 = __float2bfloat16(v.z), h3 = __float2bfloat16(v.w);
    __nv_bfloat16 l0 = __float2bfloat16(v.x - __bfloat162float(h0));
    __nv_bfloat16 l1 = __float2bfloat16(v.y - __bfloat162float(h1));
    __nv_bfloat16 l2 = __float2bfloat16(v.z - __bfloat162float(h2));
    __nv_bfloat16 l3 = __float2bfloat16(v.w - __bfloat162float(h3));
    *(__nv_bfloat162*)(hi + i)     = __halves2bfloat162(h0, h1);
    *(__nv_bfloat162*)(hi + i + 2) = __halves2bfloat162(h2, h3);
    *(__nv_bfloat162*)(lo + i)     = __halves2bfloat162(l0, l1);
    *(__nv_bfloat162*)(lo + i + 2) = __halves2bfloat162(l2, l3);
}

// Merged transpose+split for packed [Wq;Wk;Wv]^T.
__global__ void cvt_hilo_T_qkv(const float* __restrict__ Wq,
                               const float* __restrict__ Wk,
                               const float* __restrict__ Wv,
                               __nv_bfloat16* __restrict__ hiT,
                               __nv_bfloat16* __restrict__ loT)
{
    __shared__ float t[32][33];
    const int k0 = blockIdx.y * 32, n0 = blockIdx.x * 32;
    const int tx = threadIdx.x, ty = threadIdx.y;

    const float* src;
    int nn, Ns;
    if (n0 < D)            { src = Wq; nn = n0;            Ns = D;   }
    else if (n0 < D + DKV) { src = Wk; nn = n0 - D;        Ns = DKV; }
    else                   { src = Wv; nn = n0 - D - DKV;  Ns = DKV; }

#pragma unroll
    for (int i = 0; i < 4; i++)
        t[ty + i * 8][tx] = src[(size_t)(k0 + ty + i * 8) * Ns + nn + tx];
    __syncthreads();
#pragma unroll
    for (int i = 0; i < 4; i++) {
        const int r = ty + i * 8;
        float v = t[tx][r];
        __nv_bfloat16 h = __float2bfloat16(v);
        __nv_bfloat16 l = __float2bfloat16(v - __bfloat162float(h));
        hiT[(size_t)(n0 + r) * D + k0 + tx] = h;
        loT[(size_t)(n0 + r) * D + k0 + tx] = l;
    }
}

// W[K,N] row-major -> WT_hi/lo[N,K] (Wo only)
__global__ void cvt_hilo_T(const float* __restrict__ W,
                           __nv_bfloat16* __restrict__ hiT,
                           __nv_bfloat16* __restrict__ loT, int K, int N)
{
    __shared__ float t[32][33];
    const int k0 = blockIdx.y * 32, n0 = blockIdx.x * 32;
    const int tx = threadIdx.x, ty = threadIdx.y;
#pragma unroll
    for (int i = 0; i < 4; i++)
        t[ty + i * 8][tx] = W[(size_t)(k0 + ty + i * 8) * N + n0 + tx];
    __syncthreads();
#pragma unroll
    for (int i = 0; i < 4; i++) {
        const int r = ty + i * 8;
        float v = t[tx][r];
        __nv_bfloat16 h = __float2bfloat16(v);
        __nv_bfloat16 l = __float2bfloat16(v - __bfloat162float(h));
        hiT[(size_t)(n0 + r) * K + k0 + tx] = h;
        loT[(size_t)(n0 + r) * K + k0 + tx] = l;
    }
}

// ---------------------------------------------------------------------------
// bf16x3 GEMM — 128x128 CTA tile, BK=64, 3-stage smem pipeline.
// 512 threads = 16 warps (4x4), warp tile 32x32: 4 warps/SMSP for latency
// hiding (occupancy 12.5% -> 25%).
// ---------------------------------------------------------------------------
#define BK 64
#define TILE_B (128 * 128)
#define STAGE_B (4 * TILE_B)                 // 64 KB
#define NSTAGE 3
#define SMEM_GEMM (NSTAGE * STAGE_B + 128)   // ~192 KB

__global__ __launch_bounds__(512, 1) void gemm_mma(
    const __nv_bfloat16* __restrict__ Ahi, const __nv_bfloat16* __restrict__ Alo,
    const __nv_bfloat16* __restrict__ Bhi, const __nv_bfloat16* __restrict__ Blo,
    float* __restrict__ C, int N, int K)
{
    extern __shared__ char smem_raw[];
    uint32_t sb = (smem_u32(smem_raw) + 127) & ~127u;

    const int tid  = threadIdx.x;
    const int wid  = tid >> 5;
    const int lane = tid & 31;
    const int wm   = wid >> 2;          // 0..3
    const int wn   = wid & 3;           // 0..3
    const int m0   = blockIdx.y * 128;
    const int n0   = blockIdx.x * 128;

    const __nv_bfloat16* srcs[4] = {
        Ahi + (size_t)m0 * K, Alo + (size_t)m0 * K,
        Bhi + (size_t)n0 * K, Blo + (size_t)n0 * K };

    const int NK = K / BK;   // 32

    auto issue_stage = [&](int ks, int st) {
        const int k0 = ks * BK;
        const uint32_t so = sb + st * STAGE_B;
#pragma unroll
        for (int mat = 0; mat < 4; mat++) {
            const __nv_bfloat16* bp = srcs[mat] + k0;
#pragma unroll
            for (int j = 0; j < 2; j++) {
                const int idx = j * 512 + tid;          // 0..1023
                const int r   = idx >> 3;
                const int ch  = idx & 7;
                const uint32_t dst = so + mat * TILE_B + r * 128 + ((ch ^ (r & 7)) << 4);
                cp_async16(dst, bp + (size_t)r * K + ch * 8);
            }
        }
    };

    issue_stage(0, 0); cp_commit();
    issue_stage(1, 1); cp_commit();
    issue_stage(2, 2); cp_commit();

    float acc[2][4][4];
#pragma unroll
    for (int i = 0; i < 2; i++)
#pragma unroll
        for (int j = 0; j < 4; j++)
#pragma unroll
            for (int k = 0; k < 4; k++) acc[i][j][k] = 0.f;

    const int rA = wm * 32 + ((lane >> 3) & 1) * 8 + (lane & 7);  // + mt*16
    const int cA = lane >> 4;
    const int rB = wn * 32 + (lane >> 4) * 8 + (lane & 7);        // + p*16
    const int cB = (lane >> 3) & 1;

    int st = 0;
    for (int ks = 0; ks < NK; ks++) {
        const uint32_t so = sb + st * STAGE_B;
        cp_wait2();
        __syncthreads();

        const uint32_t tAh = so;
        const uint32_t tAl = so + TILE_B;
        const uint32_t tBh = so + 2 * TILE_B;
        const uint32_t tBl = so + 3 * TILE_B;

#pragma unroll
        for (int kk = 0; kk < 4; kk++) {
            uint32_t ah[2][4], al[2][4], bh[8], bl[8];
#pragma unroll
            for (int mt = 0; mt < 2; mt++) {
                const int r = rA + mt * 16;
                const int ch = kk * 2 + cA;
                const uint32_t off = r * 128 + ((ch ^ (r & 7)) << 4);
                ldsm_x4(ah[mt], tAh + off);
                ldsm_x4(al[mt], tAl + off);
            }
#pragma unroll
            for (int p = 0; p < 2; p++) {
                const int r = rB + p * 16;
                const int ch = kk * 2 + cB;
                const uint32_t off = r * 128 + ((ch ^ (r & 7)) << 4);
                ldsm_x4(&bh[p * 4], tBh + off);
                ldsm_x4(&bl[p * 4], tBl + off);
            }
#pragma unroll
            for (int mt = 0; mt < 2; mt++)
#pragma unroll
                for (int nt = 0; nt < 4; nt++)
                    mma16816(acc[mt][nt], ah[mt], &bh[nt * 2]);   // hi*hi
#pragma unroll
            for (int mt = 0; mt < 2; mt++)
#pragma unroll
                for (int nt = 0; nt < 4; nt++)
                    mma16816(acc[mt][nt], ah[mt], &bl[nt * 2]);   // hi*lo
#pragma unroll
            for (int mt = 0; mt < 2; mt++)
#pragma unroll
                for (int nt = 0; nt < 4; nt++)
                    mma16816(acc[mt][nt], al[mt], &bh[nt * 2]);   // lo*hi
        }
        __syncthreads();
        if (ks + NSTAGE < NK) issue_stage(ks + NSTAGE, st);
        cp_commit();
        st = (st + 1 == NSTAGE) ? 0 : st + 1;
    }

    const int cr = lane >> 2;
    const int cc = (lane & 3) * 2;
#pragma unroll
    for (int mt = 0; mt < 2; mt++) {
        const int rowb = m0 + wm * 32 + mt * 16 + cr;
#pragma unroll
        for (int nt = 0; nt < 4; nt++) {
            const int col = n0 + wn * 32 + nt * 8 + cc;
            *(float2*)(C + (size_t)rowb * N + col) =
                make_float2(acc[mt][nt][0], acc[mt][nt][1]);
            *(float2*)(C + (size_t)(rowb + 8) * N + col) =
                make_float2(acc[mt][nt][2], acc[mt][nt][3]);
        }
    }
}

// ---------------------------------------------------------------------------
// Fused RMSNorm + RoPE + hi/lo split for Q.
// ---------------------------------------------------------------------------
__global__ void rmsrope_q_cvt(const float* __restrict__ X,
                              __nv_bfloat16* __restrict__ Hi,
                              __nv_bfloat16* __restrict__ Lo,
                              const float* __restrict__ cosT,
                              const float* __restrict__ sinT,
                              const float* __restrict__ g)
{
    const int w = (blockIdx.x * blockDim.x + threadIdx.x) >> 5;
    const int lane = threadIdx.x & 31;
    const int s = w / NQ;
    const int h = w % NQ;

    const float* row = X + (size_t)s * DQKV + h * HD;
    float v1 = row[lane];
    float v2 = row[lane + 32];

    float ss = v1 * v1 + v2 * v2;
#pragma unroll
    for (int o = 16; o; o >>= 1) ss += __shfl_xor_sync(0xffffffffu, ss, o);

    const float r = rsqrtf(ss * (1.f / 64.f) + 1e-6f);
    const float a = v1 * r * g[lane];
    const float b = v2 * r * g[lane + 32];
    const float c  = cosT[s * 32 + lane];
    const float sn = sinT[s * 32 + lane];
    const float o1 = a * c - b * sn;
    const float o2 = a * sn + b * c;

    const size_t base = (size_t)s * D + h * HD;
    __nv_bfloat16 h1 = __float2bfloat16(o1), h2 = __float2bfloat16(o2);
    Hi[base + lane]      = h1;
    Hi[base + lane + 32] = h2;
    Lo[base + lane]      = __float2bfloat16(o1 - __bfloat162float(h1));
    Lo[base + lane + 32] = __float2bfloat16(o2 - __bfloat162float(h2));
}

__global__ void rmsrope_kv_cvt(const float* __restrict__ X,
                               __nv_bfloat16* __restrict__ Hi,
                               __nv_bfloat16* __restrict__ Lo,
                               const float* __restrict__ cosT,
                               const float* __restrict__ sinT,
                               const float* __restrict__ g)
{
    const int w = (blockIdx.x * blockDim.x + threadIdx.x) >> 5;
    const int lane = threadIdx.x & 31;
    const int s = w / NKV;
    const int h = w % NKV;

    const size_t src_k = (size_t)s * DQKV + h * HD;
    float v1 = X[src_k + lane];
    float v2 = X[src_k + lane + 32];

    float ss = v1 * v1 + v2 * v2;
#pragma unroll
    for (int o = 16; o; o >>= 1) ss += __shfl_xor_sync(0xffffffffu, ss, o);

    const float r = rsqrtf(ss * (1.f / 64.f) + 1e-6f);
    const float a = v1 * r * g[lane];
    const float b = v2 * r * g[lane + 32];
    const float c  = cosT[s * 32 + lane];
    const float sn = sinT[s * 32 + lane];
    const float o1 = a * c - b * sn;
    const float o2 = a * sn + b * c;

    const size_t dst_k = (size_t)s * KVS + h * HD;
    __nv_bfloat16 h1 = __float2bfloat16(o1), h2 = __float2bfloat16(o2);
    Hi[dst_k + lane]      = h1;
    Hi[dst_k + lane + 32] = h2;
    Lo[dst_k + lane]      = __float2bfloat16(o1 - __bfloat162float(h1));
    Lo[dst_k + lane + 32] = __float2bfloat16(o2 - __bfloat162float(h2));

    const size_t src_v = src_k + DKV;
    const size_t dst_v = dst_k + DKV;
    const float w1 = X[src_v + lane];
    const float w2 = X[src_v + lane + 32];
    __nv_bfloat16 q1 = __float2bfloat16(w1), q2 = __float2bfloat16(w2);
    Hi[dst_v + lane]      = q1;
    Hi[dst_v + lane + 32] = q2;
    Lo[dst_v + lane]      = __float2bfloat16(w1 - __bfloat162float(q1));
    Lo[dst_v + lane + 32] = __float2bfloat16(w2 - __bfloat162float(q2));
}

// ---------------------------------------------------------------------------
// Tensor-core causal GQA flash attention (bf16x3, fp32 softmax). Unchanged.
// ---------------------------------------------------------------------------
#define ATQ 128
#define ATK 64
#define AQL_OFF   16384
#define ASTG_OFF  32768
#define ASTG_SZ   32768
#define SMEM_ATTN (ASTG_OFF + 2 * ASTG_SZ + 128)

__global__ __launch_bounds__(256, 1) void attn_tc(
    const __nv_bfloat16* __restrict__ Qhi, const __nv_bfloat16* __restrict__ Qlo,
    const __nv_bfloat16* __restrict__ KVhi, const __nv_bfloat16* __restrict__ KVlo,
    __nv_bfloat16* __restrict__ Ohi, __nv_bfloat16* __restrict__ Olo)
{
    extern __shared__ char smem_raw[];
    const uint32_t sb = (smem_u32(smem_raw) + 127) & ~127u;
    const int tid = threadIdx.x, wid = tid >> 5, lane = tid & 31;
    const int h = blockIdx.y, hk = h >> 2;
    const int qb = gridDim.x - 1 - blockIdx.x;
    const int q0 = qb * ATQ;
    const int g = lane >> 2, tig = lane & 3;

    {
        const __nv_bfloat16* qsrc[2] = { Qhi + (size_t)q0 * D + h * HD,
                                         Qlo + (size_t)q0 * D + h * HD };
#pragma unroll
        for (int mat = 0; mat < 2; mat++)
#pragma unroll
            for (int j = 0; j < 4; j++) {
                const int idx = j * 256 + tid;
                const int r = idx >> 3, ch = idx & 7;
                const uint32_t dst = sb + mat * AQL_OFF + r * 128 + ((ch ^ (r & 7)) << 4);
                cp_async16(dst, qsrc[mat] + (size_t)r * D + ch * 8);
            }
    }
    cp_commit();

    const int ntile = (q0 + ATQ) / ATK;

    auto issue_kv = [&](int t, int st) {
        const int kb = t * ATK;
        const uint32_t so = sb + ASTG_OFF + st * ASTG_SZ;
        const __nv_bfloat16* bases[4] = {
            KVhi + (size_t)kb * KVS + hk * HD,
            KVlo + (size_t)kb * KVS + hk * HD,
            KVhi + (size_t)kb * KVS + DKV + hk * HD,
            KVlo + (size_t)kb * KVS + DKV + hk * HD };
#pragma unroll
        for (int mat = 0; mat < 4; mat++)
#pragma unroll
            for (int j = 0; j < 2; j++) {
                const int idx = j * 256 + tid;
                const int r = idx >> 3, ch = idx & 7;
                const uint32_t dst = so + mat * 8192 + r * 128 + ((ch ^ (r & 7)) << 4);
                cp_async16(dst, bases[mat] + (size_t)r * KVS + ch * 8);
            }
    };

    issue_kv(0, 0); cp_commit();

    cp_wait1();
    __syncthreads();

    uint32_t qh[4][4], ql[4][4];
    {
        const int r = wid * 16 + (lane & 15);
        const int chb = lane >> 4;
#pragma unroll
        for (int kk = 0; kk < 4; kk++) {
            const int ch = kk * 2 + chb;
            const uint32_t off = r * 128 + ((ch ^ (r & 7)) << 4);
            ldsm_x4(qh[kk], sb + off);
            ldsm_x4(ql[kk], sb + AQL_OFF + off);
        }
    }

    float acc_o[8][4];
#pragma unroll
    for (int i = 0; i < 8; i++)
#pragma unroll
        for (int j = 0; j < 4; j++) acc_o[i][j] = 0.f;
    float m0 = -1e30f, m1 = -1e30f, l0 = 0.f, l1 = 0.f;

    const int row0 = q0 + wid * 16 + g;
    const int row1 = row0 + 8;
    const float SCL = 0.125f * 1.44269504088896f;

    for (int t = 0; t < ntile; t++) {
        if (t + 1 < ntile) { issue_kv(t + 1, (t + 1) & 1); cp_commit(); cp_wait1(); }
        else cp_wait0();
        __syncthreads();

        const uint32_t so = sb + ASTG_OFF + (t & 1) * ASTG_SZ;
        const int kb = t * ATK;

        float sc[8][4];
#pragma unroll
        for (int i = 0; i < 8; i++)
#pragma unroll
            for (int j = 0; j < 4; j++) sc[i][j] = 0.f;

        {
            const int rbase = ((lane >> 4) & 1) * 8 + (lane & 7);
            const int chb = (lane >> 3) & 1;
#pragma unroll
            for (int kk = 0; kk < 4; kk++)
#pragma unroll
                for (int i = 0; i < 4; i++) {
                    const int r = i * 16 + rbase;
                    const int ch = kk * 2 + chb;
                    const uint32_t off = r * 128 + ((ch ^ (r & 7)) << 4);
                    uint32_t bh[4], bl[4];
                    ldsm_x4(bh, so + off);
                    ldsm_x4(bl, so + 8192 + off);
                    mma16816(sc[2 * i],     qh[kk], &bh[0]);
                    mma16816(sc[2 * i],     qh[kk], &bl[0]);
                    mma16816(sc[2 * i],     ql[kk], &bh[0]);
                    mma16816(sc[2 * i + 1], qh[kk], &bh[2]);
                    mma16816(sc[2 * i + 1], qh[kk], &bl[2]);
                    mma16816(sc[2 * i + 1], ql[kk], &bh[2]);
                }
        }

        const bool diag = (kb >= q0);
        float nm0 = m0, nm1 = m1;
#pragma unroll
        for (int nt = 0; nt < 8; nt++) {
            const int colb = kb + nt * 8 + 2 * tig;
            float t0 = sc[nt][0] * SCL, t1 = sc[nt][1] * SCL;
            float t2 = sc[nt][2] * SCL, t3 = sc[nt][3] * SCL;
            if (diag) {
                if (colb     > row0) t0 = -1e30f;
                if (colb + 1 > row0) t1 = -1e30f;
                if (colb     > row1) t2 = -1e30f;
                if (colb + 1 > row1) t3 = -1e30f;
            }
            sc[nt][0] = t0; sc[nt][1] = t1; sc[nt][2] = t2; sc[nt][3] = t3;
            nm0 = fmaxf(nm0, fmaxf(t0, t1));
            nm1 = fmaxf(nm1, fmaxf(t2, t3));
        }
        nm0 = fmaxf(nm0, __shfl_xor_sync(0xffffffffu, nm0, 1));
        nm0 = fmaxf(nm0, __shfl_xor_sync(0xffffffffu, nm0, 2));
        nm1 = fmaxf(nm1, __shfl_xor_sync(0xffffffffu, nm1, 1));
        nm1 = fmaxf(nm1, __shfl_xor_sync(0xffffffffu, nm1, 2));
        const float c0 = exp2f(m0 - nm0), c1 = exp2f(m1 - nm1);
        m0 = nm0; m1 = nm1;
        l0 *= c0; l1 *= c1;
#pragma unroll
        for (int nt = 0; nt < 8; nt++) {
            acc_o[nt][0] *= c0; acc_o[nt][1] *= c0;
            acc_o[nt][2] *= c1; acc_o[nt][3] *= c1;
        }
#pragma unroll
        for (int nt = 0; nt < 8; nt++) {
            const float p0 = exp2f(sc[nt][0] - m0), p1 = exp2f(sc[nt][1] - m0);
            const float p2 = exp2f(sc[nt][2] - m1), p3 = exp2f(sc[nt][3] - m1);
            l0 += p0 + p1; l1 += p2 + p3;
            sc[nt][0] = p0; sc[nt][1] = p1; sc[nt][2] = p2; sc[nt][3] = p3;
        }

        {
            const int rbase = ((lane >> 3) & 1) * 8 + (lane & 7);
            const int chb = lane >> 4;
#pragma unroll
            for (int kc = 0; kc < 4; kc++) {
                uint32_t aH[4], aL[4];
                pack2(sc[2 * kc][0],     sc[2 * kc][1],     aH[0], aL[0]);
                pack2(sc[2 * kc][2],     sc[2 * kc][3],     aH[1], aL[1]);
                pack2(sc[2 * kc + 1][0], sc[2 * kc + 1][1], aH[2], aL[2]);
                pack2(sc[2 * kc + 1][2], sc[2 * kc + 1][3], aH[3], aL[3]);
                const int r = kc * 16 + rbase;
#pragma unroll
                for (int j = 0; j < 4; j++) {
                    const int ch = 2 * j + chb;
                    const uint32_t off = r * 128 + ((ch ^ (r & 7)) << 4);
                    uint32_t vh[4], vl[4];
                    ldsm_x4_t(vh, so + 16384 + off);
                    ldsm_x4_t(vl, so + 24576 + off);
                    mma16816(acc_o[2 * j],     aH, &vh[0]);
                    mma16816(acc_o[2 * j],     aH, &vl[0]);
                    mma16816(acc_o[2 * j],     aL, &vh[0]);
                    mma16816(acc_o[2 * j + 1], aH, &vh[2]);
                    mma16816(acc_o[2 * j + 1], aH, &vl[2]);
                    mma16816(acc_o[2 * j + 1], aL, &vh[2]);
                }
            }
        }
        __syncthreads();
    }

    l0 += __shfl_xor_sync(0xffffffffu, l0, 1);
    l0 += __shfl_xor_sync(0xffffffffu, l0, 2);
    l1 += __shfl_xor_sync(0xffffffffu, l1, 1);
    l1 += __shfl_xor_sync(0xffffffffu, l1, 2);
    const float i0 = 1.f / l0, i1 = 1.f / l1;
    const size_t b0 = (size_t)row0 * D + h * HD;
    const size_t b1 = (size_t)row1 * D + h * HD;
#pragma unroll
    for (int nt = 0; nt < 8; nt++) {
        const int co = nt * 8 + 2 * tig;
        uint32_t hi, lo;
        pack2(acc_o[nt][0] * i0, acc_o[nt][1] * i0, hi, lo);
        *(uint32_t*)(Ohi + b0 + co) = hi;
        *(uint32_t*)(Olo + b0 + co) = lo;
        pack2(acc_o[nt][2] * i1, acc_o[nt][3] * i1, hi, lo);
        *(uint32_t*)(Ohi + b1 + co) = hi;
        *(uint32_t*)(Olo + b1 + co) = lo;
    }
}

// ---------------------------------------------------------------------------
// Launcher — launch #3 (0-indexed) is gemm_qkv so ncu captures it.
// ---------------------------------------------------------------------------
extern "C" void kernel_launch(void* const* d_in, const int* in_sizes, int n_in,
                              void* d_out, int out_size)
{
    const float* x    = (const float*)d_in[0];
    const float* cosT = (const float*)d_in[1];
    const float* sinT = (const float*)d_in[2];
    const float* gq   = (const float*)d_in[3];
    const float* gk   = (const float*)d_in[4];
    const float* Wq   = (const float*)d_in[5];
    const float* Wk   = (const float*)d_in[6];
    const float* Wv   = (const float*)d_in[7];
    const float* Wo   = (const float*)d_in[8];
    float* out = (float*)d_out;

    float* QKV;
    cudaGetSymbolAddress((void**)&QKV, g_QKV);
    __nv_bfloat16 *Ahi, *Alo, *KVhi, *KVlo, *Ohi, *Olo;
    __nv_bfloat16 *WqkvTh, *WqkvTl, *WoTh, *WoTl;
    cudaGetSymbolAddress((void**)&Ahi,    g_Ahi);
    cudaGetSymbolAddress((void**)&Alo,    g_Alo);
    cudaGetSymbolAddress((void**)&KVhi,   g_KVhi);
    cudaGetSymbolAddress((void**)&KVlo,   g_KVlo);
    cudaGetSymbolAddress((void**)&Ohi,    g_Ohi);
    cudaGetSymbolAddress((void**)&Olo,    g_Olo);
    cudaGetSymbolAddress((void**)&WqkvTh, g_WqkvThi);
    cudaGetSymbolAddress((void**)&WqkvTl, g_WqkvTlo);
    cudaGetSymbolAddress((void**)&WoTh,   g_WoThi);
    cudaGetSymbolAddress((void**)&WoTl,   g_WoTlo);

    cudaFuncSetAttribute(gemm_mma, cudaFuncAttributeMaxDynamicSharedMemorySize, SMEM_GEMM);
    cudaFuncSetAttribute(attn_tc,  cudaFuncAttributeMaxDynamicSharedMemorySize, SMEM_ATTN);

    // #0: x split
    cvt_hilo<<<(S * D / 4 + 255) / 256, 256>>>(x, Ahi, Alo, S * D);
    // #1: merged Wq|Wk|Wv transpose+split
    cvt_hilo_T_qkv<<<dim3(DQKV / 32, D / 32), dim3(32, 8)>>>(Wq, Wk, Wv, WqkvTh, WqkvTl);
    // #2: Wo transpose+split
    cvt_hilo_T<<<dim3(D / 32, D / 32), dim3(32, 8)>>>(Wo, WoTh, WoTl, D, D);

    // #3: fused QKV projection (ncu capture slot)
    gemm_mma<<<dim3(DQKV / 128, S / 128), 512, SMEM_GEMM>>>(Ahi, Alo, WqkvTh, WqkvTl,
                                                            QKV, DQKV, D);

    // #4, #5: fused RMSNorm + RoPE + hi/lo split
    rmsrope_q_cvt<<<(S * NQ)  / 8, 256>>>(QKV,     Ahi,  Alo,  cosT, sinT, gq);
    rmsrope_kv_cvt<<<(S * NKV) / 8, 256>>>(QKV + D, KVhi, KVlo, cosT, sinT, gk);

    // #6: tensor-core causal GQA attention
    attn_tc<<<dim3(S / ATQ, NQ), 256, SMEM_ATTN>>>(Ahi, Alo, KVhi, KVlo, Ohi, Olo);

    // #7: output projection
    gemm_mma<<<dim3(D / 128, S / 128), 512, SMEM_GEMM>>>(Ohi, Olo, WoTh, WoTl, out, D, D);
}

// round 12
// speedup vs baseline: 1.0260x; 1.0260x over previous
#include <cuda_runtime.h>
#include <cuda_bf16.h>
#include <math_constants.h>
#include <cstdint>

// ---------------------------------------------------------------------------
// Problem constants
// ---------------------------------------------------------------------------
#define S    2048
#define D    2048
#define NQ   32
#define NKV  8
#define HD   64
#define DKV  (NKV * HD)    // 512
#define KVS  (2 * DKV)     // 1024: packed K|V row stride
#define DQKV (D + KVS)     // 3072: packed Q|K|V projection width

// ---------------------------------------------------------------------------
// Scratch (device globals: no allocation allowed)
// ---------------------------------------------------------------------------
__device__ __nv_bfloat16 g_Ahi[S * D], g_Alo[S * D];            // x hi/lo, then Q hi/lo
__device__ __nv_bfloat16 g_KVhi[S * KVS], g_KVlo[S * KVS];      // K|V hi/lo (post norm)
__device__ __nv_bfloat16 g_Ohi[S * D], g_Olo[S * D];            // attention out hi/lo
__device__ __nv_bfloat16 g_WqkvThi[DQKV * D], g_WqkvTlo[DQKV * D]; // [Wq;Wk;Wv]^T
__device__ __nv_bfloat16 g_WoThi[D * D], g_WoTlo[D * D];        // Wo^T

// ---------------------------------------------------------------------------
// PTX helpers (base ISA only)
// ---------------------------------------------------------------------------
__device__ __forceinline__ uint32_t smem_u32(const void* p) {
    uint32_t a;
    asm("{ .reg .u64 t; cvta.to.shared.u64 t, %1; cvt.u32.u64 %0, t; }" : "=r"(a) : "l"(p));
    return a;
}
__device__ __forceinline__ void cp_async16(uint32_t dst, const void* src) {
    asm volatile("cp.async.cg.shared.global [%0], [%1], 16;" :: "r"(dst), "l"(src));
}
__device__ __forceinline__ void cp_commit() {
    asm volatile("cp.async.commit_group;" ::: "memory");
}
__device__ __forceinline__ void cp_wait2() {
    asm volatile("cp.async.wait_group 2;" ::: "memory");
}
__device__ __forceinline__ void cp_wait1() {
    asm volatile("cp.async.wait_group 1;" ::: "memory");
}
__device__ __forceinline__ void cp_wait0() {
    asm volatile("cp.async.wait_group 0;" ::: "memory");
}
__device__ __forceinline__ void ldsm_x4(uint32_t* r, uint32_t addr) {
    asm volatile("ldmatrix.sync.aligned.m8n8.x4.shared.b16 {%0,%1,%2,%3}, [%4];"
                 : "=r"(r[0]), "=r"(r[1]), "=r"(r[2]), "=r"(r[3]) : "r"(addr));
}
__device__ __forceinline__ void ldsm_x4_t(uint32_t* r, uint32_t addr) {
    asm volatile("ldmatrix.sync.aligned.m8n8.x4.trans.shared.b16 {%0,%1,%2,%3}, [%4];"
                 : "=r"(r[0]), "=r"(r[1]), "=r"(r[2]), "=r"(r[3]) : "r"(addr));
}
__device__ __forceinline__ void mma16816(float* c, const uint32_t* a, const uint32_t* b) {
    asm volatile(
        "mma.sync.aligned.m16n8k16.row.col.f32.bf16.bf16.f32 "
        "{%0,%1,%2,%3}, {%4,%5,%6,%7}, {%8,%9}, {%0,%1,%2,%3};"
        : "+f"(c[0]), "+f"(c[1]), "+f"(c[2]), "+f"(c[3])
        : "r"(a[0]), "r"(a[1]), "r"(a[2]), "r"(a[3]), "r"(b[0]), "r"(b[1]));
}
__device__ __forceinline__ void pack2(float x, float y, uint32_t& hi, uint32_t& lo) {
    __nv_bfloat16 hx = __float2bfloat16(x), hy = __float2bfloat16(y);
    __nv_bfloat162 hh = __halves2bfloat162(hx, hy);
    hi = *reinterpret_cast<uint32_t*>(&hh);
    __nv_bfloat162 ll = __halves2bfloat162(__float2bfloat16(x - __bfloat162float(hx)),
                                           __float2bfloat16(y - __bfloat162float(hy)));
    lo = *reinterpret_cast<uint32_t*>(&ll);
}

// ---------------------------------------------------------------------------
// Split-fp32 conversion kernels (input x + weights)
// ---------------------------------------------------------------------------
__global__ void cvt_hilo(const float* __restrict__ src,
                         __nv_bfloat16* __restrict__ hi,
                         __nv_bfloat16* __restrict__ lo, int n)
{
    int i = (blockIdx.x * blockDim.x + threadIdx.x) * 4;
    if (i >= n) return;
    float4 v = *(const float4*)(src + i);
    __nv_bfloat16 h0 = __float2bfloat16(v.x), h1 = __float2bfloat16(v.y);
    __nv_bfloat16 h2 = __float2bfloat16(v.z), h3 = __float2bfloat16(v.w);
    __nv_bfloat16 l0 = __float2bfloat16(v.x - __bfloat162float(h0));
    __nv_bfloat16 l1 = __float2bfloat16(v.y - __bfloat162float(h1));
    __nv_bfloat16 l2 = __float2bfloat16(v.z - __bfloat162float(h2));
    __nv_bfloat16 l3 = __float2bfloat16(v.w - __bfloat162float(h3));
    *(__nv_bfloat162*)(hi + i)     = __halves2bfloat162(h0, h1);
    *(__nv_bfloat162*)(hi + i + 2) = __halves2bfloat162(h2, h3);
    *(__nv_bfloat162*)(lo + i)     = __halves2bfloat162(l0, l1);
    *(__nv_bfloat162*)(lo + i + 2) = __halves2bfloat162(l2, l3);
}

// Merged transpose+split for packed [Wq;Wk;Wv]^T.
__global__ void cvt_hilo_T_qkv(const float* __restrict__ Wq,
                               const float* __restrict__ Wk,
                               const float* __restrict__ Wv,
                               __nv_bfloat16* __restrict__ hiT,
                               __nv_bfloat16* __restrict__ loT)
{
    __shared__ float t[32][33];
    const int k0 = blockIdx.y * 32, n0 = blockIdx.x * 32;
    const int tx = threadIdx.x, ty = threadIdx.y;

    const float* src;
    int nn, Ns;
    if (n0 < D)            { src = Wq; nn = n0;            Ns = D;   }
    else if (n0 < D + DKV) { src = Wk; nn = n0 - D;        Ns = DKV; }
    else                   { src = Wv; nn = n0 - D - DKV;  Ns = DKV; }

#pragma unroll
    for (int i = 0; i < 4; i++)
        t[ty + i * 8][tx] = src[(size_t)(k0 + ty + i * 8) * Ns + nn + tx];
    __syncthreads();
#pragma unroll
    for (int i = 0; i < 4; i++) {
        const int r = ty + i * 8;
        float v = t[tx][r];
        __nv_bfloat16 h = __float2bfloat16(v);
        __nv_bfloat16 l = __float2bfloat16(v - __bfloat162float(h));
        hiT[(size_t)(n0 + r) * D + k0 + tx] = h;
        loT[(size_t)(n0 + r) * D + k0 + tx] = l;
    }
}

// W[K,N] row-major -> WT_hi/lo[N,K] (Wo only)
__global__ void cvt_hilo_T(const float* __restrict__ W,
                           __nv_bfloat16* __restrict__ hiT,
                           __nv_bfloat16* __restrict__ loT, int K, int N)
{
    __shared__ float t[32][33];
    const int k0 = blockIdx.y * 32, n0 = blockIdx.x * 32;
    const int tx = threadIdx.x, ty = threadIdx.y;
#pragma unroll
    for (int i = 0; i < 4; i++)
        t[ty + i * 8][tx] = W[(size_t)(k0 + ty + i * 8) * N + n0 + tx];
    __syncthreads();
#pragma unroll
    for (int i = 0; i < 4; i++) {
        const int r = ty + i * 8;
        float v = t[tx][r];
        __nv_bfloat16 h = __float2bfloat16(v);
        __nv_bfloat16 l = __float2bfloat16(v - __bfloat162float(h));
        hiT[(size_t)(n0 + r) * K + k0 + tx] = h;
        loT[(size_t)(n0 + r) * K + k0 + tx] = l;
    }
}

// ---------------------------------------------------------------------------
// bf16x3 GEMM — 128x128 CTA tile, BK=64, 3-stage pipeline, 256 threads,
// 8 warps in 4(m) x 2(n): warp tile 32 rows x 64 cols (one full head wide).
// FUSED=0: plain fp32 C store (Wo projection).
// FUSED=1: fused RMSNorm+RoPE+hi/lo epilogue writing Q (Ahi/Alo) and K|V
//          (KVhi/KVlo) directly. Grid x: [0,16)=Q, [16,20)=K, [20,24)=V.
// ---------------------------------------------------------------------------
#define BK 64
#define TILE_B (128 * 128)
#define STAGE_B (4 * TILE_B)                 // 64 KB
#define NSTAGE 3
#define SMEM_GEMM (NSTAGE * STAGE_B + 128)   // ~192 KB

template<int FUSED>
__global__ __launch_bounds__(256, 1) void gemm_mma(
    const __nv_bfloat16* __restrict__ Ahi, const __nv_bfloat16* __restrict__ Alo,
    const __nv_bfloat16* __restrict__ Bhi, const __nv_bfloat16* __restrict__ Blo,
    float* __restrict__ C,
    __nv_bfloat16* __restrict__ QHi, __nv_bfloat16* __restrict__ QLo,
    __nv_bfloat16* __restrict__ KVHi, __nv_bfloat16* __restrict__ KVLo,
    const float* __restrict__ cosT, const float* __restrict__ sinT,
    const float* __restrict__ gq, const float* __restrict__ gk,
    int N, int K)
{
    extern __shared__ char smem_raw[];
    uint32_t sb = (smem_u32(smem_raw) + 127) & ~127u;

    const int tid  = threadIdx.x;
    const int wid  = tid >> 5;
    const int lane = tid & 31;
    const int wm   = wid >> 1;          // 0..3  (32 rows each)
    const int wn   = wid & 1;           // 0..1  (64 cols each)
    const int m0   = blockIdx.y * 128;
    const int n0   = blockIdx.x * 128;

    const __nv_bfloat16* srcs[4] = {
        Ahi + (size_t)m0 * K, Alo + (size_t)m0 * K,
        Bhi + (size_t)n0 * K, Blo + (size_t)n0 * K };

    const int NK = K / BK;   // 32

    auto issue_stage = [&](int ks, int st) {
        const int k0 = ks * BK;
        const uint32_t so = sb + st * STAGE_B;
#pragma unroll
        for (int mat = 0; mat < 4; mat++) {
            const __nv_bfloat16* bp = srcs[mat] + k0;
#pragma unroll
            for (int j = 0; j < 4; j++) {
                const int idx = j * 256 + tid;
                const int r   = idx >> 3;
                const int ch  = idx & 7;
                const uint32_t dst = so + mat * TILE_B + r * 128 + ((ch ^ (r & 7)) << 4);
                cp_async16(dst, bp + (size_t)r * K + ch * 8);
            }
        }
    };

    issue_stage(0, 0); cp_commit();
    issue_stage(1, 1); cp_commit();
    issue_stage(2, 2); cp_commit();

    float acc[2][8][4];
#pragma unroll
    for (int i = 0; i < 2; i++)
#pragma unroll
        for (int j = 0; j < 8; j++)
#pragma unroll
            for (int k = 0; k < 4; k++) acc[i][j][k] = 0.f;

    const int rA = wm * 32 + ((lane >> 3) & 1) * 8 + (lane & 7);  // + mt*16
    const int cA = lane >> 4;
    const int rB = wn * 64 + (lane >> 4) * 8 + (lane & 7);        // + p*16
    const int cB = (lane >> 3) & 1;

    int st = 0;
    for (int ks = 0; ks < NK; ks++) {
        const uint32_t so = sb + st * STAGE_B;
        cp_wait2();
        __syncthreads();

        const uint32_t tAh = so;
        const uint32_t tAl = so + TILE_B;
        const uint32_t tBh = so + 2 * TILE_B;
        const uint32_t tBl = so + 3 * TILE_B;

#pragma unroll
        for (int kk = 0; kk < 4; kk++) {
            uint32_t ah[2][4], al[2][4], bh[16], bl[16];
#pragma unroll
            for (int mt = 0; mt < 2; mt++) {
                const int r = rA + mt * 16;
                const int ch = kk * 2 + cA;
                const uint32_t off = r * 128 + ((ch ^ (r & 7)) << 4);
                ldsm_x4(ah[mt], tAh + off);
                ldsm_x4(al[mt], tAl + off);
            }
#pragma unroll
            for (int p = 0; p < 4; p++) {
                const int r = rB + p * 16;
                const int ch = kk * 2 + cB;
                const uint32_t off = r * 128 + ((ch ^ (r & 7)) << 4);
                ldsm_x4(&bh[p * 4], tBh + off);
                ldsm_x4(&bl[p * 4], tBl + off);
            }
#pragma unroll
            for (int mt = 0; mt < 2; mt++)
#pragma unroll
                for (int nt = 0; nt < 8; nt++)
                    mma16816(acc[mt][nt], ah[mt], &bh[nt * 2]);   // hi*hi
#pragma unroll
            for (int mt = 0; mt < 2; mt++)
#pragma unroll
                for (int nt = 0; nt < 8; nt++)
                    mma16816(acc[mt][nt], ah[mt], &bl[nt * 2]);   // hi*lo
#pragma unroll
            for (int mt = 0; mt < 2; mt++)
#pragma unroll
                for (int nt = 0; nt < 8; nt++)
                    mma16816(acc[mt][nt], al[mt], &bh[nt * 2]);   // lo*hi
        }
        __syncthreads();
        if (ks + NSTAGE < NK) issue_stage(ks + NSTAGE, st);
        cp_commit();
        st = (st + 1 == NSTAGE) ? 0 : st + 1;
    }

    const int cr  = lane >> 2;
    const int tig = lane & 3;
    const int cc  = tig * 2;

    if (FUSED == 0) {
#pragma unroll
        for (int mt = 0; mt < 2; mt++) {
            const int rowb = m0 + wm * 32 + mt * 16 + cr;
#pragma unroll
            for (int nt = 0; nt < 8; nt++) {
                const int col = n0 + wn * 64 + nt * 8 + cc;
                *(float2*)(C + (size_t)rowb * N + col) =
                    make_float2(acc[mt][nt][0], acc[mt][nt][1]);
                *(float2*)(C + (size_t)(rowb + 8) * N + col) =
                    make_float2(acc[mt][nt][2], acc[mt][nt][3]);
            }
        }
    } else {
        const int bx = blockIdx.x;
        const bool isQ = (bx < 16);
        const bool donorm = (bx < 20);            // Q and K get RMSNorm+RoPE
        __nv_bfloat16* Hi = isQ ? QHi : KVHi;
        __nv_bfloat16* Lo = isQ ? QLo : KVLo;
        const int ostride = isQ ? D : KVS;
        const int colbase = (isQ ? n0 : n0 - D) + wn * 64;
        const float* g = isQ ? gq : gk;

#pragma unroll
        for (int mt = 0; mt < 2; mt++) {
#pragma unroll
            for (int half = 0; half < 2; half++) {
                const int k0 = half * 2;
                const int row = m0 + wm * 32 + mt * 16 + cr + half * 8;
                if (donorm) {
                    float ss = 0.f;
#pragma unroll
                    for (int nt = 0; nt < 8; nt++)
                        ss += acc[mt][nt][k0] * acc[mt][nt][k0]
                            + acc[mt][nt][k0 + 1] * acc[mt][nt][k0 + 1];
                    ss += __shfl_xor_sync(0xffffffffu, ss, 1);
                    ss += __shfl_xor_sync(0xffffffffu, ss, 2);
                    const float rr = rsqrtf(ss * (1.f / 64.f) + 1e-6f);
#pragma unroll
                    for (int nt = 0; nt < 4; nt++) {
                        const int d0 = nt * 8 + cc;
                        const float x1a = acc[mt][nt][k0]     * rr * g[d0];
                        const float x1b = acc[mt][nt][k0 + 1] * rr * g[d0 + 1];
                        const float x2a = acc[mt][nt + 4][k0]     * rr * g[d0 + 32];
                        const float x2b = acc[mt][nt + 4][k0 + 1] * rr * g[d0 + 33];
                        const float ca = cosT[row * 32 + d0];
                        const float cb = cosT[row * 32 + d0 + 1];
                        const float sa = sinT[row * 32 + d0];
                        const float sbn = sinT[row * 32 + d0 + 1];
                        uint32_t h, l;
                        pack2(x1a * ca - x2a * sa, x1b * cb - x2b * sbn, h, l);
                        *(uint32_t*)(Hi + (size_t)row * ostride + colbase + d0) = h;
                        *(uint32_t*)(Lo + (size_t)row * ostride + colbase + d0) = l;
                        pack2(x1a * sa + x2a * ca, x1b * sbn + x2b * cb, h, l);
                        *(uint32_t*)(Hi + (size_t)row * ostride + colbase + d0 + 32) = h;
                        *(uint32_t*)(Lo + (size_t)row * ostride + colbase + d0 + 32) = l;
                    }
                } else {
#pragma unroll
                    for (int nt = 0; nt < 8; nt++) {
                        uint32_t h, l;
                        pack2(acc[mt][nt][k0], acc[mt][nt][k0 + 1], h, l);
                        const int col = colbase + nt * 8 + cc;
                        *(uint32_t*)(Hi + (size_t)row * ostride + col) = h;
                        *(uint32_t*)(Lo + (size_t)row * ostride + col) = l;
                    }
                }
            }
        }
    }
}

// ---------------------------------------------------------------------------
// Tensor-core causal GQA flash attention (bf16x3, fp32 softmax). Unchanged.
// ---------------------------------------------------------------------------
#define ATQ 128
#define ATK 64
#define AQL_OFF   16384
#define ASTG_OFF  32768
#define ASTG_SZ   32768
#define SMEM_ATTN (ASTG_OFF + 2 * ASTG_SZ + 128)

__global__ __launch_bounds__(256, 1) void attn_tc(
    const __nv_bfloat16* __restrict__ Qhi, const __nv_bfloat16* __restrict__ Qlo,
    const __nv_bfloat16* __restrict__ KVhi, const __nv_bfloat16* __restrict__ KVlo,
    __nv_bfloat16* __restrict__ Ohi, __nv_bfloat16* __restrict__ Olo)
{
    extern __shared__ char smem_raw[];
    const uint32_t sb = (smem_u32(smem_raw) + 127) & ~127u;
    const int tid = threadIdx.x, wid = tid >> 5, lane = tid & 31;
    const int h = blockIdx.y, hk = h >> 2;
    const int qb = gridDim.x - 1 - blockIdx.x;
    const int q0 = qb * ATQ;
    const int g = lane >> 2, tig = lane & 3;

    {
        const __nv_bfloat16* qsrc[2] = { Qhi + (size_t)q0 * D + h * HD,
                                         Qlo + (size_t)q0 * D + h * HD };
#pragma unroll
        for (int mat = 0; mat < 2; mat++)
#pragma unroll
            for (int j = 0; j < 4; j++) {
                const int idx = j * 256 + tid;
                const int r = idx >> 3, ch = idx & 7;
                const uint32_t dst = sb + mat * AQL_OFF + r * 128 + ((ch ^ (r & 7)) << 4);
                cp_async16(dst, qsrc[mat] + (size_t)r * D + ch * 8);
            }
    }
    cp_commit();

    const int ntile = (q0 + ATQ) / ATK;

    auto issue_kv = [&](int t, int st) {
        const int kb = t * ATK;
        const uint32_t so = sb + ASTG_OFF + st * ASTG_SZ;
        const __nv_bfloat16* bases[4] = {
            KVhi + (size_t)kb * KVS + hk * HD,
            KVlo + (size_t)kb * KVS + hk * HD,
            KVhi + (size_t)kb * KVS + DKV + hk * HD,
            KVlo + (size_t)kb * KVS + DKV + hk * HD };
#pragma unroll
        for (int mat = 0; mat < 4; mat++)
#pragma unroll
            for (int j = 0; j < 2; j++) {
                const int idx = j * 256 + tid;
                const int r = idx >> 3, ch = idx & 7;
                const uint32_t dst = so + mat * 8192 + r * 128 + ((ch ^ (r & 7)) << 4);
                cp_async16(dst, bases[mat] + (size_t)r * KVS + ch * 8);
            }
    };

    issue_kv(0, 0); cp_commit();

    cp_wait1();
    __syncthreads();

    uint32_t qh[4][4], ql[4][4];
    {
        const int r = wid * 16 + (lane & 15);
        const int chb = lane >> 4;
#pragma unroll
        for (int kk = 0; kk < 4; kk++) {
            const int ch = kk * 2 + chb;
            const uint32_t off = r * 128 + ((ch ^ (r & 7)) << 4);
            ldsm_x4(qh[kk], sb + off);
            ldsm_x4(ql[kk], sb + AQL_OFF + off);
        }
    }

    float acc_o[8][4];
#pragma unroll
    for (int i = 0; i < 8; i++)
#pragma unroll
        for (int j = 0; j < 4; j++) acc_o[i][j] = 0.f;
    float m0 = -1e30f, m1 = -1e30f, l0 = 0.f, l1 = 0.f;

    const int row0 = q0 + wid * 16 + g;
    const int row1 = row0 + 8;
    const float SCL = 0.125f * 1.44269504088896f;

    for (int t = 0; t < ntile; t++) {
        if (t + 1 < ntile) { issue_kv(t + 1, (t + 1) & 1); cp_commit(); cp_wait1(); }
        else cp_wait0();
        __syncthreads();

        const uint32_t so = sb + ASTG_OFF + (t & 1) * ASTG_SZ;
        const int kb = t * ATK;

        float sc[8][4];
#pragma unroll
        for (int i = 0; i < 8; i++)
#pragma unroll
            for (int j = 0; j < 4; j++) sc[i][j] = 0.f;

        {
            const int rbase = ((lane >> 4) & 1) * 8 + (lane & 7);
            const int chb = (lane >> 3) & 1;
#pragma unroll
            for (int kk = 0; kk < 4; kk++)
#pragma unroll
                for (int i = 0; i < 4; i++) {
                    const int r = i * 16 + rbase;
                    const int ch = kk * 2 + chb;
                    const uint32_t off = r * 128 + ((ch ^ (r & 7)) << 4);
                    uint32_t bh[4], bl[4];
                    ldsm_x4(bh, so + off);
                    ldsm_x4(bl, so + 8192 + off);
                    mma16816(sc[2 * i],     qh[kk], &bh[0]);
                    mma16816(sc[2 * i],     qh[kk], &bl[0]);
                    mma16816(sc[2 * i],     ql[kk], &bh[0]);
                    mma16816(sc[2 * i + 1], qh[kk], &bh[2]);
                    mma16816(sc[2 * i + 1], qh[kk], &bl[2]);
                    mma16816(sc[2 * i + 1], ql[kk], &bh[2]);
                }
        }

        const bool diag = (kb >= q0);
        float nm0 = m0, nm1 = m1;
#pragma unroll
        for (int nt = 0; nt < 8; nt++) {
            const int colb = kb + nt * 8 + 2 * tig;
            float t0 = sc[nt][0] * SCL, t1 = sc[nt][1] * SCL;
            float t2 = sc[nt][2] * SCL, t3 = sc[nt][3] * SCL;
            if (diag) {
                if (colb     > row0) t0 = -1e30f;
                if (colb + 1 > row0) t1 = -1e30f;
                if (colb     > row1) t2 = -1e30f;
                if (colb + 1 > row1) t3 = -1e30f;
            }
            sc[nt][0] = t0; sc[nt][1] = t1; sc[nt][2] = t2; sc[nt][3] = t3;
            nm0 = fmaxf(nm0, fmaxf(t0, t1));
            nm1 = fmaxf(nm1, fmaxf(t2, t3));
        }
        nm0 = fmaxf(nm0, __shfl_xor_sync(0xffffffffu, nm0, 1));
        nm0 = fmaxf(nm0, __shfl_xor_sync(0xffffffffu, nm0, 2));
        nm1 = fmaxf(nm1, __shfl_xor_sync(0xffffffffu, nm1, 1));
        nm1 = fmaxf(nm1, __shfl_xor_sync(0xffffffffu, nm1, 2));
        const float c0 = exp2f(m0 - nm0), c1 = exp2f(m1 - nm1);
        m0 = nm0; m1 = nm1;
        l0 *= c0; l1 *= c1;
#pragma unroll
        for (int nt = 0; nt < 8; nt++) {
            acc_o[nt][0] *= c0; acc_o[nt][1] *= c0;
            acc_o[nt][2] *= c1; acc_o[nt][3] *= c1;
        }
#pragma unroll
        for (int nt = 0; nt < 8; nt++) {
            const float p0 = exp2f(sc[nt][0] - m0), p1 = exp2f(sc[nt][1] - m0);
            const float p2 = exp2f(sc[nt][2] - m1), p3 = exp2f(sc[nt][3] - m1);
            l0 += p0 + p1; l1 += p2 + p3;
            sc[nt][0] = p0; sc[nt][1] = p1; sc[nt][2] = p2; sc[nt][3] = p3;
        }

        {
            const int rbase = ((lane >> 3) & 1) * 8 + (lane & 7);
            const int chb = lane >> 4;
#pragma unroll
            for (int kc = 0; kc < 4; kc++) {
                uint32_t aH[4], aL[4];
                pack2(sc[2 * kc][0],     sc[2 * kc][1],     aH[0], aL[0]);
                pack2(sc[2 * kc][2],     sc[2 * kc][3],     aH[1], aL[1]);
                pack2(sc[2 * kc + 1][0], sc[2 * kc + 1][1], aH[2], aL[2]);
                pack2(sc[2 * kc + 1][2], sc[2 * kc + 1][3], aH[3], aL[3]);
                const int r = kc * 16 + rbase;
#pragma unroll
                for (int j = 0; j < 4; j++) {
                    const int ch = 2 * j + chb;
                    const uint32_t off = r * 128 + ((ch ^ (r & 7)) << 4);
                    uint32_t vh[4], vl[4];
                    ldsm_x4_t(vh, so + 16384 + off);
                    ldsm_x4_t(vl, so + 24576 + off);
                    mma16816(acc_o[2 * j],     aH, &vh[0]);
                    mma16816(acc_o[2 * j],     aH, &vl[0]);
                    mma16816(acc_o[2 * j],     aL, &vh[0]);
                    mma16816(acc_o[2 * j + 1], aH, &vh[2]);
                    mma16816(acc_o[2 * j + 1], aH, &vl[2]);
                    mma16816(acc_o[2 * j + 1], aL, &vh[2]);
                }
            }
        }
        __syncthreads();
    }

    l0 += __shfl_xor_sync(0xffffffffu, l0, 1);
    l0 += __shfl_xor_sync(0xffffffffu, l0, 2);
    l1 += __shfl_xor_sync(0xffffffffu, l1, 1);
    l1 += __shfl_xor_sync(0xffffffffu, l1, 2);
    const float i0 = 1.f / l0, i1 = 1.f / l1;
    const size_t b0 = (size_t)row0 * D + h * HD;
    const size_t b1 = (size_t)row1 * D + h * HD;
#pragma unroll
    for (int nt = 0; nt < 8; nt++) {
        const int co = nt * 8 + 2 * tig;
        uint32_t hi, lo;
        pack2(acc_o[nt][0] * i0, acc_o[nt][1] * i0, hi, lo);
        *(uint32_t*)(Ohi + b0 + co) = hi;
        *(uint32_t*)(Olo + b0 + co) = lo;
        pack2(acc_o[nt][2] * i1, acc_o[nt][3] * i1, hi, lo);
        *(uint32_t*)(Ohi + b1 + co) = hi;
        *(uint32_t*)(Olo + b1 + co) = lo;
    }
}

// ---------------------------------------------------------------------------
// Launcher — attention is launch #3 (0-indexed) => ncu capture slot.
// ---------------------------------------------------------------------------
extern "C" void kernel_launch(void* const* d_in, const int* in_sizes, int n_in,
                              void* d_out, int out_size)
{
    const float* x    = (const float*)d_in[0];
    const float* cosT = (const float*)d_in[1];
    const float* sinT = (const float*)d_in[2];
    const float* gq   = (const float*)d_in[3];
    const float* gk   = (const float*)d_in[4];
    const float* Wq   = (const float*)d_in[5];
    const float* Wk   = (const float*)d_in[6];
    const float* Wv   = (const float*)d_in[7];
    const float* Wo   = (const float*)d_in[8];
    float* out = (float*)d_out;

    __nv_bfloat16 *Ahi, *Alo, *KVhi, *KVlo, *Ohi, *Olo;
    __nv_bfloat16 *WqkvTh, *WqkvTl, *WoTh, *WoTl;
    cudaGetSymbolAddress((void**)&Ahi,    g_Ahi);
    cudaGetSymbolAddress((void**)&Alo,    g_Alo);
    cudaGetSymbolAddress((void**)&KVhi,   g_KVhi);
    cudaGetSymbolAddress((void**)&KVlo,   g_KVlo);
    cudaGetSymbolAddress((void**)&Ohi,    g_Ohi);
    cudaGetSymbolAddress((void**)&Olo,    g_Olo);
    cudaGetSymbolAddress((void**)&WqkvTh, g_WqkvThi);
    cudaGetSymbolAddress((void**)&WqkvTl, g_WqkvTlo);
    cudaGetSymbolAddress((void**)&WoTh,   g_WoThi);
    cudaGetSymbolAddress((void**)&WoTl,   g_WoTlo);

    cudaFuncSetAttribute(gemm_mma<0>, cudaFuncAttributeMaxDynamicSharedMemorySize, SMEM_GEMM);
    cudaFuncSetAttribute(gemm_mma<1>, cudaFuncAttributeMaxDynamicSharedMemorySize, SMEM_GEMM);
    cudaFuncSetAttribute(attn_tc,     cudaFuncAttributeMaxDynamicSharedMemorySize, SMEM_ATTN);

    // #0: x split
    cvt_hilo<<<(S * D / 4 + 255) / 256, 256>>>(x, Ahi, Alo, S * D);
    // #1: merged Wq|Wk|Wv transpose+split
    cvt_hilo_T_qkv<<<dim3(DQKV / 32, D / 32), dim3(32, 8)>>>(Wq, Wk, Wv, WqkvTh, WqkvTl);

    // #2: fused QKV projection + RMSNorm + RoPE + hi/lo epilogue.
    //     NOTE: reads Ahi/Alo (x) fully before any CTA writes Q rows into the
    //     same buffers? NO — writes alias the input! Use Ohi/Olo as Q output
    //     (free until attention) to avoid the race.
    gemm_mma<1><<<dim3(DQKV / 128, S / 128), 256, SMEM_GEMM>>>(
        Ahi, Alo, WqkvTh, WqkvTl, nullptr,
        Ohi, Olo, KVhi, KVlo, cosT, sinT, gq, gk, DQKV, D);

    // #3: attention (ncu capture slot). Q lives in Ohi/Olo; output -> Ahi/Alo
    //     (x is dead after the QKV GEMM completes).
    attn_tc<<<dim3(S / ATQ, NQ), 256, SMEM_ATTN>>>(Ohi, Olo, KVhi, KVlo, Ahi, Alo);

    // #4: Wo transpose+split
    cvt_hilo_T<<<dim3(D / 32, D / 32), dim3(32, 8)>>>(Wo, WoTh, WoTl, D, D);

    // #5: output projection (plain fp32 epilogue)
    gemm_mma<0><<<dim3(D / 128, S / 128), 256, SMEM_GEMM>>>(
        Ahi, Alo, WoTh, WoTl, out,
        nullptr, nullptr, nullptr, nullptr, nullptr, nullptr, nullptr, nullptr, D, D);
}

// round 13
// speedup vs baseline: 1.0369x; 1.0106x over previous
#include <cuda_runtime.h>
#include <cuda_bf16.h>
#include <math_constants.h>
#include <cstdint>

// ---------------------------------------------------------------------------
// Problem constants
// ---------------------------------------------------------------------------
#define S    2048
#define D    2048
#define NQ   32
#define NKV  8
#define HD   64
#define DKV  (NKV * HD)    // 512
#define KVS  (2 * DKV)     // 1024: packed K|V row stride
#define DQKV (D + KVS)     // 3072: packed Q|K|V projection width

// ---------------------------------------------------------------------------
// Scratch (device globals: no allocation allowed)
// ---------------------------------------------------------------------------
__device__ __nv_bfloat16 g_Ahi[S * D], g_Alo[S * D];            // x hi/lo -> attn out
__device__ __nv_bfloat16 g_KVhi[S * KVS], g_KVlo[S * KVS];      // K|V hi/lo (post norm)
__device__ __nv_bfloat16 g_Ohi[S * D], g_Olo[S * D];            // Q hi/lo (post norm/rope)
__device__ __nv_bfloat16 g_WqkvThi[DQKV * D], g_WqkvTlo[DQKV * D]; // [Wq;Wk;Wv]^T
__device__ __nv_bfloat16 g_WoThi[D * D], g_WoTlo[D * D];        // Wo^T

// ---------------------------------------------------------------------------
// PTX helpers (base ISA only)
// ---------------------------------------------------------------------------
__device__ __forceinline__ uint32_t smem_u32(const void* p) {
    uint32_t a;
    asm("{ .reg .u64 t; cvta.to.shared.u64 t, %1; cvt.u32.u64 %0, t; }" : "=r"(a) : "l"(p));
    return a;
}
__device__ __forceinline__ void cp_async16(uint32_t dst, const void* src) {
    asm volatile("cp.async.cg.shared.global [%0], [%1], 16;" :: "r"(dst), "l"(src));
}
__device__ __forceinline__ void cp_commit() {
    asm volatile("cp.async.commit_group;" ::: "memory");
}
__device__ __forceinline__ void cp_wait2() {
    asm volatile("cp.async.wait_group 2;" ::: "memory");
}
__device__ __forceinline__ void cp_wait1() {
    asm volatile("cp.async.wait_group 1;" ::: "memory");
}
__device__ __forceinline__ void cp_wait0() {
    asm volatile("cp.async.wait_group 0;" ::: "memory");
}
__device__ __forceinline__ void ldsm_x4(uint32_t* r, uint32_t addr) {
    asm volatile("ldmatrix.sync.aligned.m8n8.x4.shared.b16 {%0,%1,%2,%3}, [%4];"
                 : "=r"(r[0]), "=r"(r[1]), "=r"(r[2]), "=r"(r[3]) : "r"(addr));
}
__device__ __forceinline__ void ldsm_x4_t(uint32_t* r, uint32_t addr) {
    asm volatile("ldmatrix.sync.aligned.m8n8.x4.trans.shared.b16 {%0,%1,%2,%3}, [%4];"
                 : "=r"(r[0]), "=r"(r[1]), "=r"(r[2]), "=r"(r[3]) : "r"(addr));
}
__device__ __forceinline__ void mma16816(float* c, const uint32_t* a, const uint32_t* b) {
    asm volatile(
        "mma.sync.aligned.m16n8k16.row.col.f32.bf16.bf16.f32 "
        "{%0,%1,%2,%3}, {%4,%5,%6,%7}, {%8,%9}, {%0,%1,%2,%3};"
        : "+f"(c[0]), "+f"(c[1]), "+f"(c[2]), "+f"(c[3])
        : "r"(a[0]), "r"(a[1]), "r"(a[2]), "r"(a[3]), "r"(b[0]), "r"(b[1]));
}
__device__ __forceinline__ float ex2(float x) {   // guaranteed single MUFU
    float y;
    asm("ex2.approx.f32 %0, %1;" : "=f"(y) : "f"(x));
    return y;
}
__device__ __forceinline__ void pack2(float x, float y, uint32_t& hi, uint32_t& lo) {
    __nv_bfloat16 hx = __float2bfloat16(x), hy = __float2bfloat16(y);
    __nv_bfloat162 hh = __halves2bfloat162(hx, hy);
    hi = *reinterpret_cast<uint32_t*>(&hh);
    __nv_bfloat162 ll = __halves2bfloat162(__float2bfloat16(x - __bfloat162float(hx)),
                                           __float2bfloat16(y - __bfloat162float(hy)));
    lo = *reinterpret_cast<uint32_t*>(&ll);
}

// ---------------------------------------------------------------------------
// Split-fp32 conversion kernels (input x + weights)
// ---------------------------------------------------------------------------
__global__ void cvt_hilo(const float* __restrict__ src,
                         __nv_bfloat16* __restrict__ hi,
                         __nv_bfloat16* __restrict__ lo, int n)
{
    int i = (blockIdx.x * blockDim.x + threadIdx.x) * 4;
    if (i >= n) return;
    float4 v = *(const float4*)(src + i);
    __nv_bfloat16 h0 = __float2bfloat16(v.x), h1 = __float2bfloat16(v.y);
    __nv_bfloat16 h2 = __float2bfloat16(v.z), h3 = __float2bfloat16(v.w);
    __nv_bfloat16 l0 = __float2bfloat16(v.x - __bfloat162float(h0));
    __nv_bfloat16 l1 = __float2bfloat16(v.y - __bfloat162float(h1));
    __nv_bfloat16 l2 = __float2bfloat16(v.z - __bfloat162float(h2));
    __nv_bfloat16 l3 = __float2bfloat16(v.w - __bfloat162float(h3));
    *(__nv_bfloat162*)(hi + i)     = __halves2bfloat162(h0, h1);
    *(__nv_bfloat162*)(hi + i + 2) = __halves2bfloat162(h2, h3);
    *(__nv_bfloat162*)(lo + i)     = __halves2bfloat162(l0, l1);
    *(__nv_bfloat162*)(lo + i + 2) = __halves2bfloat162(l2, l3);
}

// Merged transpose+split for packed [Wq;Wk;Wv]^T.
__global__ void cvt_hilo_T_qkv(const float* __restrict__ Wq,
                               const float* __restrict__ Wk,
                               const float* __restrict__ Wv,
                               __nv_bfloat16* __restrict__ hiT,
                               __nv_bfloat16* __restrict__ loT)
{
    __shared__ float t[32][33];
    const int k0 = blockIdx.y * 32, n0 = blockIdx.x * 32;
    const int tx = threadIdx.x, ty = threadIdx.y;

    const float* src;
    int nn, Ns;
    if (n0 < D)            { src = Wq; nn = n0;            Ns = D;   }
    else if (n0 < D + DKV) { src = Wk; nn = n0 - D;        Ns = DKV; }
    else                   { src = Wv; nn = n0 - D - DKV;  Ns = DKV; }

#pragma unroll
    for (int i = 0; i < 4; i++)
        t[ty + i * 8][tx] = src[(size_t)(k0 + ty + i * 8) * Ns + nn + tx];
    __syncthreads();
#pragma unroll
    for (int i = 0; i < 4; i++) {
        const int r = ty + i * 8;
        float v = t[tx][r];
        __nv_bfloat16 h = __float2bfloat16(v);
        __nv_bfloat16 l = __float2bfloat16(v - __bfloat162float(h));
        hiT[(size_t)(n0 + r) * D + k0 + tx] = h;
        loT[(size_t)(n0 + r) * D + k0 + tx] = l;
    }
}

// W[K,N] row-major -> WT_hi/lo[N,K] (Wo only)
__global__ void cvt_hilo_T(const float* __restrict__ W,
                           __nv_bfloat16* __restrict__ hiT,
                           __nv_bfloat16* __restrict__ loT, int K, int N)
{
    __shared__ float t[32][33];
    const int k0 = blockIdx.y * 32, n0 = blockIdx.x * 32;
    const int tx = threadIdx.x, ty = threadIdx.y;
#pragma unroll
    for (int i = 0; i < 4; i++)
        t[ty + i * 8][tx] = W[(size_t)(k0 + ty + i * 8) * N + n0 + tx];
    __syncthreads();
#pragma unroll
    for (int i = 0; i < 4; i++) {
        const int r = ty + i * 8;
        float v = t[tx][r];
        __nv_bfloat16 h = __float2bfloat16(v);
        __nv_bfloat16 l = __float2bfloat16(v - __bfloat162float(h));
        hiT[(size_t)(n0 + r) * K + k0 + tx] = h;
        loT[(size_t)(n0 + r) * K + k0 + tx] = l;
    }
}

// ---------------------------------------------------------------------------
// bf16x3 GEMM — 128x128 CTA tile, BK=64, 3-stage pipeline, 256 threads,
// 8 warps in 4(m) x 2(n): warp tile 32 rows x 64 cols.
// FUSED=0: plain fp32 C store (Wo). FUSED=1: RMSNorm+RoPE+hi/lo epilogue.
// ---------------------------------------------------------------------------
#define BK 64
#define TILE_B (128 * 128)
#define STAGE_B (4 * TILE_B)                 // 64 KB
#define NSTAGE 3
#define SMEM_GEMM (NSTAGE * STAGE_B + 128)   // ~192 KB

template<int FUSED>
__global__ __launch_bounds__(256, 1) void gemm_mma(
    const __nv_bfloat16* __restrict__ Ahi, const __nv_bfloat16* __restrict__ Alo,
    const __nv_bfloat16* __restrict__ Bhi, const __nv_bfloat16* __restrict__ Blo,
    float* __restrict__ C,
    __nv_bfloat16* __restrict__ QHi, __nv_bfloat16* __restrict__ QLo,
    __nv_bfloat16* __restrict__ KVHi, __nv_bfloat16* __restrict__ KVLo,
    const float* __restrict__ cosT, const float* __restrict__ sinT,
    const float* __restrict__ gq, const float* __restrict__ gk,
    int N, int K)
{
    extern __shared__ char smem_raw[];
    uint32_t sb = (smem_u32(smem_raw) + 127) & ~127u;

    const int tid  = threadIdx.x;
    const int wid  = tid >> 5;
    const int lane = tid & 31;
    const int wm   = wid >> 1;
    const int wn   = wid & 1;
    const int m0   = blockIdx.y * 128;
    const int n0   = blockIdx.x * 128;

    const __nv_bfloat16* srcs[4] = {
        Ahi + (size_t)m0 * K, Alo + (size_t)m0 * K,
        Bhi + (size_t)n0 * K, Blo + (size_t)n0 * K };

    const int NK = K / BK;

    auto issue_stage = [&](int ks, int st) {
        const int k0 = ks * BK;
        const uint32_t so = sb + st * STAGE_B;
#pragma unroll
        for (int mat = 0; mat < 4; mat++) {
            const __nv_bfloat16* bp = srcs[mat] + k0;
#pragma unroll
            for (int j = 0; j < 4; j++) {
                const int idx = j * 256 + tid;
                const int r   = idx >> 3;
                const int ch  = idx & 7;
                const uint32_t dst = so + mat * TILE_B + r * 128 + ((ch ^ (r & 7)) << 4);
                cp_async16(dst, bp + (size_t)r * K + ch * 8);
            }
        }
    };

    issue_stage(0, 0); cp_commit();
    issue_stage(1, 1); cp_commit();
    issue_stage(2, 2); cp_commit();

    float acc[2][8][4];
#pragma unroll
    for (int i = 0; i < 2; i++)
#pragma unroll
        for (int j = 0; j < 8; j++)
#pragma unroll
            for (int k = 0; k < 4; k++) acc[i][j][k] = 0.f;

    const int rA = wm * 32 + ((lane >> 3) & 1) * 8 + (lane & 7);
    const int cA = lane >> 4;
    const int rB = wn * 64 + (lane >> 4) * 8 + (lane & 7);
    const int cB = (lane >> 3) & 1;

    int st = 0;
    for (int ks = 0; ks < NK; ks++) {
        const uint32_t so = sb + st * STAGE_B;
        cp_wait2();
        __syncthreads();

        const uint32_t tAh = so;
        const uint32_t tAl = so + TILE_B;
        const uint32_t tBh = so + 2 * TILE_B;
        const uint32_t tBl = so + 3 * TILE_B;

#pragma unroll
        for (int kk = 0; kk < 4; kk++) {
            uint32_t ah[2][4], al[2][4], bh[16], bl[16];
#pragma unroll
            for (int mt = 0; mt < 2; mt++) {
                const int r = rA + mt * 16;
                const int ch = kk * 2 + cA;
                const uint32_t off = r * 128 + ((ch ^ (r & 7)) << 4);
                ldsm_x4(ah[mt], tAh + off);
                ldsm_x4(al[mt], tAl + off);
            }
#pragma unroll
            for (int p = 0; p < 4; p++) {
                const int r = rB + p * 16;
                const int ch = kk * 2 + cB;
                const uint32_t off = r * 128 + ((ch ^ (r & 7)) << 4);
                ldsm_x4(&bh[p * 4], tBh + off);
                ldsm_x4(&bl[p * 4], tBl + off);
            }
#pragma unroll
            for (int mt = 0; mt < 2; mt++)
#pragma unroll
                for (int nt = 0; nt < 8; nt++)
                    mma16816(acc[mt][nt], ah[mt], &bh[nt * 2]);
#pragma unroll
            for (int mt = 0; mt < 2; mt++)
#pragma unroll
                for (int nt = 0; nt < 8; nt++)
                    mma16816(acc[mt][nt], ah[mt], &bl[nt * 2]);
#pragma unroll
            for (int mt = 0; mt < 2; mt++)
#pragma unroll
                for (int nt = 0; nt < 8; nt++)
                    mma16816(acc[mt][nt], al[mt], &bh[nt * 2]);
        }
        __syncthreads();
        if (ks + NSTAGE < NK) issue_stage(ks + NSTAGE, st);
        cp_commit();
        st = (st + 1 == NSTAGE) ? 0 : st + 1;
    }

    const int cr  = lane >> 2;
    const int tig = lane & 3;
    const int cc  = tig * 2;

    if (FUSED == 0) {
#pragma unroll
        for (int mt = 0; mt < 2; mt++) {
            const int rowb = m0 + wm * 32 + mt * 16 + cr;
#pragma unroll
            for (int nt = 0; nt < 8; nt++) {
                const int col = n0 + wn * 64 + nt * 8 + cc;
                *(float2*)(C + (size_t)rowb * N + col) =
                    make_float2(acc[mt][nt][0], acc[mt][nt][1]);
                *(float2*)(C + (size_t)(rowb + 8) * N + col) =
                    make_float2(acc[mt][nt][2], acc[mt][nt][3]);
            }
        }
    } else {
        const int bx = blockIdx.x;
        const bool isQ = (bx < 16);
        const bool donorm = (bx < 20);
        __nv_bfloat16* Hi = isQ ? QHi : KVHi;
        __nv_bfloat16* Lo = isQ ? QLo : KVLo;
        const int ostride = isQ ? D : KVS;
        const int colbase = (isQ ? n0 : n0 - D) + wn * 64;
        const float* g = isQ ? gq : gk;

#pragma unroll
        for (int mt = 0; mt < 2; mt++) {
#pragma unroll
            for (int half = 0; half < 2; half++) {
                const int k0 = half * 2;
                const int row = m0 + wm * 32 + mt * 16 + cr + half * 8;
                if (donorm) {
                    float ss = 0.f;
#pragma unroll
                    for (int nt = 0; nt < 8; nt++)
                        ss += acc[mt][nt][k0] * acc[mt][nt][k0]
                            + acc[mt][nt][k0 + 1] * acc[mt][nt][k0 + 1];
                    ss += __shfl_xor_sync(0xffffffffu, ss, 1);
                    ss += __shfl_xor_sync(0xffffffffu, ss, 2);
                    const float rr = rsqrtf(ss * (1.f / 64.f) + 1e-6f);
#pragma unroll
                    for (int nt = 0; nt < 4; nt++) {
                        const int d0 = nt * 8 + cc;
                        const float x1a = acc[mt][nt][k0]     * rr * g[d0];
                        const float x1b = acc[mt][nt][k0 + 1] * rr * g[d0 + 1];
                        const float x2a = acc[mt][nt + 4][k0]     * rr * g[d0 + 32];
                        const float x2b = acc[mt][nt + 4][k0 + 1] * rr * g[d0 + 33];
                        const float ca = cosT[row * 32 + d0];
                        const float cb = cosT[row * 32 + d0 + 1];
                        const float sa = sinT[row * 32 + d0];
                        const float sbn = sinT[row * 32 + d0 + 1];
                        uint32_t h, l;
                        pack2(x1a * ca - x2a * sa, x1b * cb - x2b * sbn, h, l);
                        *(uint32_t*)(Hi + (size_t)row * ostride + colbase + d0) = h;
                        *(uint32_t*)(Lo + (size_t)row * ostride + colbase + d0) = l;
                        pack2(x1a * sa + x2a * ca, x1b * sbn + x2b * cb, h, l);
                        *(uint32_t*)(Hi + (size_t)row * ostride + colbase + d0 + 32) = h;
                        *(uint32_t*)(Lo + (size_t)row * ostride + colbase + d0 + 32) = l;
                    }
                } else {
#pragma unroll
                    for (int nt = 0; nt < 8; nt++) {
                        uint32_t h, l;
                        pack2(acc[mt][nt][k0], acc[mt][nt][k0 + 1], h, l);
                        const int col = colbase + nt * 8 + cc;
                        *(uint32_t*)(Hi + (size_t)row * ostride + col) = h;
                        *(uint32_t*)(Lo + (size_t)row * ostride + col) = l;
                    }
                }
            }
        }
    }
}

// ---------------------------------------------------------------------------
// Tensor-core causal GQA flash attention (bf16x3, fp32 softmax).
// 3-stage KV pipeline, ONE barrier per tile, ex2.approx exponentials.
// ---------------------------------------------------------------------------
#define ATQ 128
#define ATK 64
#define AQL_OFF   16384
#define ASTG_OFF  32768
#define ASTG_SZ   32768
#define ANST 3
#define SMEM_ATTN (ASTG_OFF + ANST * ASTG_SZ + 128)   // ~128KB

__global__ __launch_bounds__(256, 1) void attn_tc(
    const __nv_bfloat16* __restrict__ Qhi, const __nv_bfloat16* __restrict__ Qlo,
    const __nv_bfloat16* __restrict__ KVhi, const __nv_bfloat16* __restrict__ KVlo,
    __nv_bfloat16* __restrict__ Ohi, __nv_bfloat16* __restrict__ Olo)
{
    extern __shared__ char smem_raw[];
    const uint32_t sb = (smem_u32(smem_raw) + 127) & ~127u;
    const int tid = threadIdx.x, wid = tid >> 5, lane = tid & 31;
    const int h = blockIdx.y, hk = h >> 2;
    const int qb = gridDim.x - 1 - blockIdx.x;
    const int q0 = qb * ATQ;
    const int g = lane >> 2, tig = lane & 3;

    const int ntile = (q0 + ATQ) / ATK;

    auto issue_kv = [&](int t, int st) {
        const int kb = t * ATK;
        const uint32_t so = sb + ASTG_OFF + st * ASTG_SZ;
        const __nv_bfloat16* bases[4] = {
            KVhi + (size_t)kb * KVS + hk * HD,
            KVlo + (size_t)kb * KVS + hk * HD,
            KVhi + (size_t)kb * KVS + DKV + hk * HD,
            KVlo + (size_t)kb * KVS + DKV + hk * HD };
#pragma unroll
        for (int mat = 0; mat < 4; mat++)
#pragma unroll
            for (int j = 0; j < 2; j++) {
                const int idx = j * 256 + tid;
                const int r = idx >> 3, ch = idx & 7;
                const uint32_t dst = so + mat * 8192 + r * 128 + ((ch ^ (r & 7)) << 4);
                cp_async16(dst, bases[mat] + (size_t)r * KVS + ch * 8);
            }
    };

    // prologue: Q (group0), kv0 (group1), kv1 (group2)
    {
        const __nv_bfloat16* qsrc[2] = { Qhi + (size_t)q0 * D + h * HD,
                                         Qlo + (size_t)q0 * D + h * HD };
#pragma unroll
        for (int mat = 0; mat < 2; mat++)
#pragma unroll
            for (int j = 0; j < 4; j++) {
                const int idx = j * 256 + tid;
                const int r = idx >> 3, ch = idx & 7;
                const uint32_t dst = sb + mat * AQL_OFF + r * 128 + ((ch ^ (r & 7)) << 4);
                cp_async16(dst, qsrc[mat] + (size_t)r * D + ch * 8);
            }
    }
    cp_commit();
    issue_kv(0, 0); cp_commit();
    if (ntile > 1) issue_kv(1, 1);
    cp_commit();

    cp_wait2();        // Q complete
    __syncthreads();   // Q visible to all

    uint32_t qh[4][4], ql[4][4];
    {
        const int r = wid * 16 + (lane & 15);
        const int chb = lane >> 4;
#pragma unroll
        for (int kk = 0; kk < 4; kk++) {
            const int ch = kk * 2 + chb;
            const uint32_t off = r * 128 + ((ch ^ (r & 7)) << 4);
            ldsm_x4(qh[kk], sb + off);
            ldsm_x4(ql[kk], sb + AQL_OFF + off);
        }
    }

    float acc_o[8][4];
#pragma unroll
    for (int i = 0; i < 8; i++)
#pragma unroll
        for (int j = 0; j < 4; j++) acc_o[i][j] = 0.f;
    float m0 = -1e30f, m1 = -1e30f, l0 = 0.f, l1 = 0.f;

    const int row0 = q0 + wid * 16 + g;
    const int row1 = row0 + 8;
    const float SCL = 0.125f * 1.44269504088896f;

    int st = 0;
    for (int t = 0; t < ntile; t++) {
        cp_wait1();        // stage t complete (own copies)
        __syncthreads();   // visibility + WAR protection for stage (t+2)%3
        if (t + 2 < ntile) issue_kv(t + 2, (t + 2) % ANST);
        cp_commit();

        const uint32_t so = sb + ASTG_OFF + st * ASTG_SZ;
        const int kb = t * ATK;

        float sc[8][4];
#pragma unroll
        for (int i = 0; i < 8; i++)
#pragma unroll
            for (int j = 0; j < 4; j++) sc[i][j] = 0.f;

        {
            const int rbase = ((lane >> 4) & 1) * 8 + (lane & 7);
            const int chb = (lane >> 3) & 1;
#pragma unroll
            for (int kk = 0; kk < 4; kk++)
#pragma unroll
                for (int i = 0; i < 4; i++) {
                    const int r = i * 16 + rbase;
                    const int ch = kk * 2 + chb;
                    const uint32_t off = r * 128 + ((ch ^ (r & 7)) << 4);
                    uint32_t bh[4], bl[4];
                    ldsm_x4(bh, so + off);
                    ldsm_x4(bl, so + 8192 + off);
                    mma16816(sc[2 * i],     qh[kk], &bh[0]);
                    mma16816(sc[2 * i],     qh[kk], &bl[0]);
                    mma16816(sc[2 * i],     ql[kk], &bh[0]);
                    mma16816(sc[2 * i + 1], qh[kk], &bh[2]);
                    mma16816(sc[2 * i + 1], qh[kk], &bl[2]);
                    mma16816(sc[2 * i + 1], ql[kk], &bh[2]);
                }
        }

        const bool diag = (kb >= q0);
        float nm0 = m0, nm1 = m1;
#pragma unroll
        for (int nt = 0; nt < 8; nt++) {
            const int colb = kb + nt * 8 + 2 * tig;
            float t0 = sc[nt][0] * SCL, t1 = sc[nt][1] * SCL;
            float t2 = sc[nt][2] * SCL, t3 = sc[nt][3] * SCL;
            if (diag) {
                if (colb     > row0) t0 = -1e30f;
                if (colb + 1 > row0) t1 = -1e30f;
                if (colb     > row1) t2 = -1e30f;
                if (colb + 1 > row1) t3 = -1e30f;
            }
            sc[nt][0] = t0; sc[nt][1] = t1; sc[nt][2] = t2; sc[nt][3] = t3;
            nm0 = fmaxf(nm0, fmaxf(t0, t1));
            nm1 = fmaxf(nm1, fmaxf(t2, t3));
        }
        nm0 = fmaxf(nm0, __shfl_xor_sync(0xffffffffu, nm0, 1));
        nm0 = fmaxf(nm0, __shfl_xor_sync(0xffffffffu, nm0, 2));
        nm1 = fmaxf(nm1, __shfl_xor_sync(0xffffffffu, nm1, 1));
        nm1 = fmaxf(nm1, __shfl_xor_sync(0xffffffffu, nm1, 2));
        const float c0 = ex2(m0 - nm0), c1 = ex2(m1 - nm1);
        m0 = nm0; m1 = nm1;
        l0 *= c0; l1 *= c1;
#pragma unroll
        for (int nt = 0; nt < 8; nt++) {
            acc_o[nt][0] *= c0; acc_o[nt][1] *= c0;
            acc_o[nt][2] *= c1; acc_o[nt][3] *= c1;
        }
#pragma unroll
        for (int nt = 0; nt < 8; nt++) {
            const float p0 = ex2(sc[nt][0] - m0), p1 = ex2(sc[nt][1] - m0);
            const float p2 = ex2(sc[nt][2] - m1), p3 = ex2(sc[nt][3] - m1);
            l0 += p0 + p1; l1 += p2 + p3;
            sc[nt][0] = p0; sc[nt][1] = p1; sc[nt][2] = p2; sc[nt][3] = p3;
        }

        {
            const int rbase = ((lane >> 3) & 1) * 8 + (lane & 7);
            const int chb = lane >> 4;
#pragma unroll
            for (int kc = 0; kc < 4; kc++) {
                uint32_t aH[4], aL[4];
                pack2(sc[2 * kc][0],     sc[2 * kc][1],     aH[0], aL[0]);
                pack2(sc[2 * kc][2],     sc[2 * kc][3],     aH[1], aL[1]);
                pack2(sc[2 * kc + 1][0], sc[2 * kc + 1][1], aH[2], aL[2]);
                pack2(sc[2 * kc + 1][2], sc[2 * kc + 1][3], aH[3], aL[3]);
                const int r = kc * 16 + rbase;
#pragma unroll
                for (int j = 0; j < 4; j++) {
                    const int ch = 2 * j + chb;
                    const uint32_t off = r * 128 + ((ch ^ (r & 7)) << 4);
                    uint32_t vh[4], vl[4];
                    ldsm_x4_t(vh, so + 16384 + off);
                    ldsm_x4_t(vl, so + 24576 + off);
                    mma16816(acc_o[2 * j],     aH, &vh[0]);
                    mma16816(acc_o[2 * j],     aH, &vl[0]);
                    mma16816(acc_o[2 * j],     aL, &vh[0]);
                    mma16816(acc_o[2 * j + 1], aH, &vh[2]);
                    mma16816(acc_o[2 * j + 1], aH, &vl[2]);
                    mma16816(acc_o[2 * j + 1], aL, &vh[2]);
                }
            }
        }
        st = (st + 1 == ANST) ? 0 : st + 1;
    }

    l0 += __shfl_xor_sync(0xffffffffu, l0, 1);
    l0 += __shfl_xor_sync(0xffffffffu, l0, 2);
    l1 += __shfl_xor_sync(0xffffffffu, l1, 1);
    l1 += __shfl_xor_sync(0xffffffffu, l1, 2);
    const float i0 = 1.f / l0, i1 = 1.f / l1;
    const size_t b0 = (size_t)row0 * D + h * HD;
    const size_t b1 = (size_t)row1 * D + h * HD;
#pragma unroll
    for (int nt = 0; nt < 8; nt++) {
        const int co = nt * 8 + 2 * tig;
        uint32_t hi, lo;
        pack2(acc_o[nt][0] * i0, acc_o[nt][1] * i0, hi, lo);
        *(uint32_t*)(Ohi + b0 + co) = hi;
        *(uint32_t*)(Olo + b0 + co) = lo;
        pack2(acc_o[nt][2] * i1, acc_o[nt][3] * i1, hi, lo);
        *(uint32_t*)(Ohi + b1 + co) = hi;
        *(uint32_t*)(Olo + b1 + co) = lo;
    }
}

// ---------------------------------------------------------------------------
// Launcher — attention is launch #3 (0-indexed) => ncu capture slot.
// ---------------------------------------------------------------------------
extern "C" void kernel_launch(void* const* d_in, const int* in_sizes, int n_in,
                              void* d_out, int out_size)
{
    const float* x    = (const float*)d_in[0];
    const float* cosT = (const float*)d_in[1];
    const float* sinT = (const float*)d_in[2];
    const float* gq   = (const float*)d_in[3];
    const float* gk   = (const float*)d_in[4];
    const float* Wq   = (const float*)d_in[5];
    const float* Wk   = (const float*)d_in[6];
    const float* Wv   = (const float*)d_in[7];
    const float* Wo   = (const float*)d_in[8];
    float* out = (float*)d_out;

    __nv_bfloat16 *Ahi, *Alo, *KVhi, *KVlo, *Ohi, *Olo;
    __nv_bfloat16 *WqkvTh, *WqkvTl, *WoTh, *WoTl;
    cudaGetSymbolAddress((void**)&Ahi,    g_Ahi);
    cudaGetSymbolAddress((void**)&Alo,    g_Alo);
    cudaGetSymbolAddress((void**)&KVhi,   g_KVhi);
    cudaGetSymbolAddress((void**)&KVlo,   g_KVlo);
    cudaGetSymbolAddress((void**)&Ohi,    g_Ohi);
    cudaGetSymbolAddress((void**)&Olo,    g_Olo);
    cudaGetSymbolAddress((void**)&WqkvTh, g_WqkvThi);
    cudaGetSymbolAddress((void**)&WqkvTl, g_WqkvTlo);
    cudaGetSymbolAddress((void**)&WoTh,   g_WoThi);
    cudaGetSymbolAddress((void**)&WoTl,   g_WoTlo);

    cudaFuncSetAttribute(gemm_mma<0>, cudaFuncAttributeMaxDynamicSharedMemorySize, SMEM_GEMM);
    cudaFuncSetAttribute(gemm_mma<1>, cudaFuncAttributeMaxDynamicSharedMemorySize, SMEM_GEMM);
    cudaFuncSetAttribute(attn_tc,     cudaFuncAttributeMaxDynamicSharedMemorySize, SMEM_ATTN);

    // #0: x split
    cvt_hilo<<<(S * D / 4 + 255) / 256, 256>>>(x, Ahi, Alo, S * D);
    // #1: merged Wq|Wk|Wv transpose+split
    cvt_hilo_T_qkv<<<dim3(DQKV / 32, D / 32), dim3(32, 8)>>>(Wq, Wk, Wv, WqkvTh, WqkvTl);

    // #2: fused QKV projection + RMSNorm + RoPE + hi/lo epilogue.
    //     Q output goes to Ohi/Olo (input x lives in Ahi/Alo — no aliasing).
    gemm_mma<1><<<dim3(DQKV / 128, S / 128), 256, SMEM_GEMM>>>(
        Ahi, Alo, WqkvTh, WqkvTl, nullptr,
        Ohi, Olo, KVhi, KVlo, cosT, sinT, gq, gk, DQKV, D);

    // #3: attention (ncu capture slot). Q in Ohi/Olo; output -> Ahi/Alo.
    attn_tc<<<dim3(S / ATQ, NQ), 256, SMEM_ATTN>>>(Ohi, Olo, KVhi, KVlo, Ahi, Alo);

    // #4: Wo transpose+split
    cvt_hilo_T<<<dim3(D / 32, D / 32), dim3(32, 8)>>>(Wo, WoTh, WoTl, D, D);

    // #5: output projection (plain fp32 epilogue)
    gemm_mma<0><<<dim3(D / 128, S / 128), 256, SMEM_GEMM>>>(
        Ahi, Alo, WoTh, WoTl, out,
        nullptr, nullptr, nullptr, nullptr, nullptr, nullptr, nullptr, nullptr, D, D);
}

// round 14
// speedup vs baseline: 1.0740x; 1.0359x over previous
#include <cuda_runtime.h>
#include <cuda_bf16.h>
#include <math_constants.h>
#include <cstdint>

// ---------------------------------------------------------------------------
// Problem constants
// ---------------------------------------------------------------------------
#define S    2048
#define D    2048
#define NQ   32
#define NKV  8
#define HD   64
#define DKV  (NKV * HD)    // 512
#define KVS  (2 * DKV)     // 1024: packed K|V row stride
#define DQKV (D + KVS)     // 3072: packed Q|K|V projection width

// ---------------------------------------------------------------------------
// Scratch (device globals: no allocation allowed)
// ---------------------------------------------------------------------------
__device__ __nv_bfloat16 g_Ahi[S * D], g_Alo[S * D];            // x hi/lo -> attn out
__device__ __nv_bfloat16 g_KVhi[S * KVS], g_KVlo[S * KVS];      // K|V hi/lo (post norm)
__device__ __nv_bfloat16 g_Ohi[S * D], g_Olo[S * D];            // Q hi/lo (post norm/rope)
__device__ __nv_bfloat16 g_WqkvThi[DQKV * D], g_WqkvTlo[DQKV * D]; // [Wq;Wk;Wv]^T
__device__ __nv_bfloat16 g_WoThi[D * D], g_WoTlo[D * D];        // Wo^T

// ---------------------------------------------------------------------------
// PTX helpers (base ISA only)
// ---------------------------------------------------------------------------
__device__ __forceinline__ uint32_t smem_u32(const void* p) {
    uint32_t a;
    asm("{ .reg .u64 t; cvta.to.shared.u64 t, %1; cvt.u32.u64 %0, t; }" : "=r"(a) : "l"(p));
    return a;
}
__device__ __forceinline__ void cp_async16(uint32_t dst, const void* src) {
    asm volatile("cp.async.cg.shared.global [%0], [%1], 16;" :: "r"(dst), "l"(src));
}
__device__ __forceinline__ void cp_commit() {
    asm volatile("cp.async.commit_group;" ::: "memory");
}
__device__ __forceinline__ void cp_wait2() {
    asm volatile("cp.async.wait_group 2;" ::: "memory");
}
__device__ __forceinline__ void cp_wait1() {
    asm volatile("cp.async.wait_group 1;" ::: "memory");
}
__device__ __forceinline__ void cp_wait0() {
    asm volatile("cp.async.wait_group 0;" ::: "memory");
}
__device__ __forceinline__ void ldsm_x4(uint32_t* r, uint32_t addr) {
    asm volatile("ldmatrix.sync.aligned.m8n8.x4.shared.b16 {%0,%1,%2,%3}, [%4];"
                 : "=r"(r[0]), "=r"(r[1]), "=r"(r[2]), "=r"(r[3]) : "r"(addr));
}
__device__ __forceinline__ void ldsm_x4_t(uint32_t* r, uint32_t addr) {
    asm volatile("ldmatrix.sync.aligned.m8n8.x4.trans.shared.b16 {%0,%1,%2,%3}, [%4];"
                 : "=r"(r[0]), "=r"(r[1]), "=r"(r[2]), "=r"(r[3]) : "r"(addr));
}
__device__ __forceinline__ void mma16816(float* c, const uint32_t* a, const uint32_t* b) {
    asm volatile(
        "mma.sync.aligned.m16n8k16.row.col.f32.bf16.bf16.f32 "
        "{%0,%1,%2,%3}, {%4,%5,%6,%7}, {%8,%9}, {%0,%1,%2,%3};"
        : "+f"(c[0]), "+f"(c[1]), "+f"(c[2]), "+f"(c[3])
        : "r"(a[0]), "r"(a[1]), "r"(a[2]), "r"(a[3]), "r"(b[0]), "r"(b[1]));
}
__device__ __forceinline__ float ex2(float x) {
    float y;
    asm("ex2.approx.f32 %0, %1;" : "=f"(y) : "f"(x));
    return y;
}
__device__ __forceinline__ void pack2(float x, float y, uint32_t& hi, uint32_t& lo) {
    __nv_bfloat16 hx = __float2bfloat16(x), hy = __float2bfloat16(y);
    __nv_bfloat162 hh = __halves2bfloat162(hx, hy);
    hi = *reinterpret_cast<uint32_t*>(&hh);
    __nv_bfloat162 ll = __halves2bfloat162(__float2bfloat16(x - __bfloat162float(hx)),
                                           __float2bfloat16(y - __bfloat162float(hy)));
    lo = *reinterpret_cast<uint32_t*>(&ll);
}

// ---------------------------------------------------------------------------
// Split-fp32 conversion kernels (input x + weights)
// ---------------------------------------------------------------------------
__global__ void cvt_hilo(const float* __restrict__ src,
                         __nv_bfloat16* __restrict__ hi,
                         __nv_bfloat16* __restrict__ lo, int n)
{
    int i = (blockIdx.x * blockDim.x + threadIdx.x) * 4;
    if (i >= n) return;
    float4 v = *(const float4*)(src + i);
    __nv_bfloat16 h0 = __float2bfloat16(v.x), h1 = __float2bfloat16(v.y);
    __nv_bfloat16 h2 = __float2bfloat16(v.z), h3 = __float2bfloat16(v.w);
    __nv_bfloat16 l0 = __float2bfloat16(v.x - __bfloat162float(h0));
    __nv_bfloat16 l1 = __float2bfloat16(v.y - __bfloat162float(h1));
    __nv_bfloat16 l2 = __float2bfloat16(v.z - __bfloat162float(h2));
    __nv_bfloat16 l3 = __float2bfloat16(v.w - __bfloat162float(h3));
    *(__nv_bfloat162*)(hi + i)     = __halves2bfloat162(h0, h1);
    *(__nv_bfloat162*)(hi + i + 2) = __halves2bfloat162(h2, h3);
    *(__nv_bfloat162*)(lo + i)     = __halves2bfloat162(l0, l1);
    *(__nv_bfloat162*)(lo + i + 2) = __halves2bfloat162(l2, l3);
}

// Merged transpose+split for packed [Wq;Wk;Wv]^T.
__global__ void cvt_hilo_T_qkv(const float* __restrict__ Wq,
                               const float* __restrict__ Wk,
                               const float* __restrict__ Wv,
                               __nv_bfloat16* __restrict__ hiT,
                               __nv_bfloat16* __restrict__ loT)
{
    __shared__ float t[32][33];
    const int k0 = blockIdx.y * 32, n0 = blockIdx.x * 32;
    const int tx = threadIdx.x, ty = threadIdx.y;

    const float* src;
    int nn, Ns;
    if (n0 < D)            { src = Wq; nn = n0;            Ns = D;   }
    else if (n0 < D + DKV) { src = Wk; nn = n0 - D;        Ns = DKV; }
    else                   { src = Wv; nn = n0 - D - DKV;  Ns = DKV; }

#pragma unroll
    for (int i = 0; i < 4; i++)
        t[ty + i * 8][tx] = src[(size_t)(k0 + ty + i * 8) * Ns + nn + tx];
    __syncthreads();
#pragma unroll
    for (int i = 0; i < 4; i++) {
        const int r = ty + i * 8;
        float v = t[tx][r];
        __nv_bfloat16 h = __float2bfloat16(v);
        __nv_bfloat16 l = __float2bfloat16(v - __bfloat162float(h));
        hiT[(size_t)(n0 + r) * D + k0 + tx] = h;
        loT[(size_t)(n0 + r) * D + k0 + tx] = l;
    }
}

// W[K,N] row-major -> WT_hi/lo[N,K] (Wo only)
__global__ void cvt_hilo_T(const float* __restrict__ W,
                           __nv_bfloat16* __restrict__ hiT,
                           __nv_bfloat16* __restrict__ loT, int K, int N)
{
    __shared__ float t[32][33];
    const int k0 = blockIdx.y * 32, n0 = blockIdx.x * 32;
    const int tx = threadIdx.x, ty = threadIdx.y;
#pragma unroll
    for (int i = 0; i < 4; i++)
        t[ty + i * 8][tx] = W[(size_t)(k0 + ty + i * 8) * N + n0 + tx];
    __syncthreads();
#pragma unroll
    for (int i = 0; i < 4; i++) {
        const int r = ty + i * 8;
        float v = t[tx][r];
        __nv_bfloat16 h = __float2bfloat16(v);
        __nv_bfloat16 l = __float2bfloat16(v - __bfloat162float(h));
        hiT[(size_t)(n0 + r) * K + k0 + tx] = h;
        loT[(size_t)(n0 + r) * K + k0 + tx] = l;
    }
}

// ---------------------------------------------------------------------------
// bf16x3 GEMM — 128x128 CTA tile, BK=64, 3-stage pipeline, 256 threads,
// 8 warps in 4(m) x 2(n): warp tile 32 rows x 64 cols.
// FUSED=0: plain fp32 C store (Wo). FUSED=1: RMSNorm+RoPE+hi/lo epilogue.
// ---------------------------------------------------------------------------
#define BK 64
#define TILE_B (128 * 128)
#define STAGE_B (4 * TILE_B)                 // 64 KB
#define NSTAGE 3
#define SMEM_GEMM (NSTAGE * STAGE_B + 128)   // ~192 KB

template<int FUSED>
__global__ __launch_bounds__(256, 1) void gemm_mma(
    const __nv_bfloat16* __restrict__ Ahi, const __nv_bfloat16* __restrict__ Alo,
    const __nv_bfloat16* __restrict__ Bhi, const __nv_bfloat16* __restrict__ Blo,
    float* __restrict__ C,
    __nv_bfloat16* __restrict__ QHi, __nv_bfloat16* __restrict__ QLo,
    __nv_bfloat16* __restrict__ KVHi, __nv_bfloat16* __restrict__ KVLo,
    const float* __restrict__ cosT, const float* __restrict__ sinT,
    const float* __restrict__ gq, const float* __restrict__ gk,
    int N, int K)
{
    extern __shared__ char smem_raw[];
    uint32_t sb = (smem_u32(smem_raw) + 127) & ~127u;

    const int tid  = threadIdx.x;
    const int wid  = tid >> 5;
    const int lane = tid & 31;
    const int wm   = wid >> 1;
    const int wn   = wid & 1;
    const int m0   = blockIdx.y * 128;
    const int n0   = blockIdx.x * 128;

    const __nv_bfloat16* srcs[4] = {
        Ahi + (size_t)m0 * K, Alo + (size_t)m0 * K,
        Bhi + (size_t)n0 * K, Blo + (size_t)n0 * K };

    const int NK = K / BK;

    auto issue_stage = [&](int ks, int st) {
        const int k0 = ks * BK;
        const uint32_t so = sb + st * STAGE_B;
#pragma unroll
        for (int mat = 0; mat < 4; mat++) {
            const __nv_bfloat16* bp = srcs[mat] + k0;
#pragma unroll
            for (int j = 0; j < 4; j++) {
                const int idx = j * 256 + tid;
                const int r   = idx >> 3;
                const int ch  = idx & 7;
                const uint32_t dst = so + mat * TILE_B + r * 128 + ((ch ^ (r & 7)) << 4);
                cp_async16(dst, bp + (size_t)r * K + ch * 8);
            }
        }
    };

    issue_stage(0, 0); cp_commit();
    issue_stage(1, 1); cp_commit();
    issue_stage(2, 2); cp_commit();

    float acc[2][8][4];
#pragma unroll
    for (int i = 0; i < 2; i++)
#pragma unroll
        for (int j = 0; j < 8; j++)
#pragma unroll
            for (int k = 0; k < 4; k++) acc[i][j][k] = 0.f;

    const int rA = wm * 32 + ((lane >> 3) & 1) * 8 + (lane & 7);
    const int cA = lane >> 4;
    const int rB = wn * 64 + (lane >> 4) * 8 + (lane & 7);
    const int cB = (lane >> 3) & 1;

    int st = 0;
    for (int ks = 0; ks < NK; ks++) {
        const uint32_t so = sb + st * STAGE_B;
        cp_wait2();
        __syncthreads();

        const uint32_t tAh = so;
        const uint32_t tAl = so + TILE_B;
        const uint32_t tBh = so + 2 * TILE_B;
        const uint32_t tBl = so + 3 * TILE_B;

#pragma unroll
        for (int kk = 0; kk < 4; kk++) {
            uint32_t ah[2][4], al[2][4], bh[16], bl[16];
#pragma unroll
            for (int mt = 0; mt < 2; mt++) {
                const int r = rA + mt * 16;
                const int ch = kk * 2 + cA;
                const uint32_t off = r * 128 + ((ch ^ (r & 7)) << 4);
                ldsm_x4(ah[mt], tAh + off);
                ldsm_x4(al[mt], tAl + off);
            }
#pragma unroll
            for (int p = 0; p < 4; p++) {
                const int r = rB + p * 16;
                const int ch = kk * 2 + cB;
                const uint32_t off = r * 128 + ((ch ^ (r & 7)) << 4);
                ldsm_x4(&bh[p * 4], tBh + off);
                ldsm_x4(&bl[p * 4], tBl + off);
            }
#pragma unroll
            for (int mt = 0; mt < 2; mt++)
#pragma unroll
                for (int nt = 0; nt < 8; nt++)
                    mma16816(acc[mt][nt], ah[mt], &bh[nt * 2]);
#pragma unroll
            for (int mt = 0; mt < 2; mt++)
#pragma unroll
                for (int nt = 0; nt < 8; nt++)
                    mma16816(acc[mt][nt], ah[mt], &bl[nt * 2]);
#pragma unroll
            for (int mt = 0; mt < 2; mt++)
#pragma unroll
                for (int nt = 0; nt < 8; nt++)
                    mma16816(acc[mt][nt], al[mt], &bh[nt * 2]);
        }
        __syncthreads();
        if (ks + NSTAGE < NK) issue_stage(ks + NSTAGE, st);
        cp_commit();
        st = (st + 1 == NSTAGE) ? 0 : st + 1;
    }

    const int cr  = lane >> 2;
    const int tig = lane & 3;
    const int cc  = tig * 2;

    if (FUSED == 0) {
#pragma unroll
        for (int mt = 0; mt < 2; mt++) {
            const int rowb = m0 + wm * 32 + mt * 16 + cr;
#pragma unroll
            for (int nt = 0; nt < 8; nt++) {
                const int col = n0 + wn * 64 + nt * 8 + cc;
                *(float2*)(C + (size_t)rowb * N + col) =
                    make_float2(acc[mt][nt][0], acc[mt][nt][1]);
                *(float2*)(C + (size_t)(rowb + 8) * N + col) =
                    make_float2(acc[mt][nt][2], acc[mt][nt][3]);
            }
        }
    } else {
        const int bx = blockIdx.x;
        const bool isQ = (bx < 16);
        const bool donorm = (bx < 20);
        __nv_bfloat16* Hi = isQ ? QHi : KVHi;
        __nv_bfloat16* Lo = isQ ? QLo : KVLo;
        const int ostride = isQ ? D : KVS;
        const int colbase = (isQ ? n0 : n0 - D) + wn * 64;
        const float* g = isQ ? gq : gk;

#pragma unroll
        for (int mt = 0; mt < 2; mt++) {
#pragma unroll
            for (int half = 0; half < 2; half++) {
                const int k0 = half * 2;
                const int row = m0 + wm * 32 + mt * 16 + cr + half * 8;
                if (donorm) {
                    float ss = 0.f;
#pragma unroll
                    for (int nt = 0; nt < 8; nt++)
                        ss += acc[mt][nt][k0] * acc[mt][nt][k0]
                            + acc[mt][nt][k0 + 1] * acc[mt][nt][k0 + 1];
                    ss += __shfl_xor_sync(0xffffffffu, ss, 1);
                    ss += __shfl_xor_sync(0xffffffffu, ss, 2);
                    const float rr = rsqrtf(ss * (1.f / 64.f) + 1e-6f);
#pragma unroll
                    for (int nt = 0; nt < 4; nt++) {
                        const int d0 = nt * 8 + cc;
                        const float x1a = acc[mt][nt][k0]     * rr * g[d0];
                        const float x1b = acc[mt][nt][k0 + 1] * rr * g[d0 + 1];
                        const float x2a = acc[mt][nt + 4][k0]     * rr * g[d0 + 32];
                        const float x2b = acc[mt][nt + 4][k0 + 1] * rr * g[d0 + 33];
                        const float ca = cosT[row * 32 + d0];
                        const float cb = cosT[row * 32 + d0 + 1];
                        const float sa = sinT[row * 32 + d0];
                        const float sbn = sinT[row * 32 + d0 + 1];
                        uint32_t h, l;
                        pack2(x1a * ca - x2a * sa, x1b * cb - x2b * sbn, h, l);
                        *(uint32_t*)(Hi + (size_t)row * ostride + colbase + d0) = h;
                        *(uint32_t*)(Lo + (size_t)row * ostride + colbase + d0) = l;
                        pack2(x1a * sa + x2a * ca, x1b * sbn + x2b * cb, h, l);
                        *(uint32_t*)(Hi + (size_t)row * ostride + colbase + d0 + 32) = h;
                        *(uint32_t*)(Lo + (size_t)row * ostride + colbase + d0 + 32) = l;
                    }
                } else {
#pragma unroll
                    for (int nt = 0; nt < 8; nt++) {
                        uint32_t h, l;
                        pack2(acc[mt][nt][k0], acc[mt][nt][k0 + 1], h, l);
                        const int col = colbase + nt * 8 + cc;
                        *(uint32_t*)(Hi + (size_t)row * ostride + col) = h;
                        *(uint32_t*)(Lo + (size_t)row * ostride + col) = l;
                    }
                }
            }
        }
    }
}

// ---------------------------------------------------------------------------
// Tensor-core causal GQA flash attention (bf16x3, fp32 softmax).
// ATQ=64, 128 threads (4 warps), 2-stage KV pipeline, 80 KB smem
// => 2 CTAs per SM for cross-CTA tensor/softmax overlap.
// ---------------------------------------------------------------------------
#define ATQ 64
#define ATK 64
#define AQL_OFF   8192
#define ASTG_OFF  16384
#define ASTG_SZ   32768
#define SMEM_ATTN (ASTG_OFF + 2 * ASTG_SZ + 128)   // ~80KB -> 2 CTAs/SM

__global__ __launch_bounds__(128, 2) void attn_tc(
    const __nv_bfloat16* __restrict__ Qhi, const __nv_bfloat16* __restrict__ Qlo,
    const __nv_bfloat16* __restrict__ KVhi, const __nv_bfloat16* __restrict__ KVlo,
    __nv_bfloat16* __restrict__ Ohi, __nv_bfloat16* __restrict__ Olo)
{
    extern __shared__ char smem_raw[];
    const uint32_t sb = (smem_u32(smem_raw) + 127) & ~127u;
    const int tid = threadIdx.x, wid = tid >> 5, lane = tid & 31;
    const int h = blockIdx.y, hk = h >> 2;
    const int qb = gridDim.x - 1 - blockIdx.x;       // heavy blocks first
    const int q0 = qb * ATQ;
    const int g = lane >> 2, tig = lane & 3;

    const int ntile = (q0 + ATQ) / ATK;              // qb + 1

    auto issue_kv = [&](int t, int st) {
        const int kb = t * ATK;
        const uint32_t so = sb + ASTG_OFF + st * ASTG_SZ;
        const __nv_bfloat16* bases[4] = {
            KVhi + (size_t)kb * KVS + hk * HD,
            KVlo + (size_t)kb * KVS + hk * HD,
            KVhi + (size_t)kb * KVS + DKV + hk * HD,
            KVlo + (size_t)kb * KVS + DKV + hk * HD };
#pragma unroll
        for (int mat = 0; mat < 4; mat++)
#pragma unroll
            for (int j = 0; j < 4; j++) {
                const int idx = j * 128 + tid;        // 0..511
                const int r = idx >> 3, ch = idx & 7;
                const uint32_t dst = so + mat * 8192 + r * 128 + ((ch ^ (r & 7)) << 4);
                cp_async16(dst, bases[mat] + (size_t)r * KVS + ch * 8);
            }
    };

    // prologue: Q (64 rows x 128B, hi+lo)
    {
        const __nv_bfloat16* qsrc[2] = { Qhi + (size_t)q0 * D + h * HD,
                                         Qlo + (size_t)q0 * D + h * HD };
#pragma unroll
        for (int mat = 0; mat < 2; mat++)
#pragma unroll
            for (int j = 0; j < 4; j++) {
                const int idx = j * 128 + tid;
                const int r = idx >> 3, ch = idx & 7;
                const uint32_t dst = sb + mat * AQL_OFF + r * 128 + ((ch ^ (r & 7)) << 4);
                cp_async16(dst, qsrc[mat] + (size_t)r * D + ch * 8);
            }
    }
    cp_commit();
    issue_kv(0, 0); cp_commit();

    cp_wait1();          // Q done (kv0 may be in flight)
    __syncthreads();

    uint32_t qh[4][4], ql[4][4];
    {
        const int r = wid * 16 + (lane & 15);         // rows 0..63
        const int chb = lane >> 4;
#pragma unroll
        for (int kk = 0; kk < 4; kk++) {
            const int ch = kk * 2 + chb;
            const uint32_t off = r * 128 + ((ch ^ (r & 7)) << 4);
            ldsm_x4(qh[kk], sb + off);
            ldsm_x4(ql[kk], sb + AQL_OFF + off);
        }
    }

    float acc_o[8][4];
#pragma unroll
    for (int i = 0; i < 8; i++)
#pragma unroll
        for (int j = 0; j < 4; j++) acc_o[i][j] = 0.f;
    float m0 = -1e30f, m1 = -1e30f, l0 = 0.f, l1 = 0.f;

    const int row0 = q0 + wid * 16 + g;
    const int row1 = row0 + 8;
    const float SCL = 0.125f * 1.44269504088896f;

    for (int t = 0; t < ntile; t++) {
        if (t + 1 < ntile) { issue_kv(t + 1, (t + 1) & 1); cp_commit(); cp_wait1(); }
        else cp_wait0();
        __syncthreads();

        const uint32_t so = sb + ASTG_OFF + (t & 1) * ASTG_SZ;
        const int kb = t * ATK;

        float sc[8][4];
#pragma unroll
        for (int i = 0; i < 8; i++)
#pragma unroll
            for (int j = 0; j < 4; j++) sc[i][j] = 0.f;

        {
            const int rbase = ((lane >> 4) & 1) * 8 + (lane & 7);
            const int chb = (lane >> 3) & 1;
#pragma unroll
            for (int kk = 0; kk < 4; kk++)
#pragma unroll
                for (int i = 0; i < 4; i++) {
                    const int r = i * 16 + rbase;
                    const int ch = kk * 2 + chb;
                    const uint32_t off = r * 128 + ((ch ^ (r & 7)) << 4);
                    uint32_t bh[4], bl[4];
                    ldsm_x4(bh, so + off);
                    ldsm_x4(bl, so + 8192 + off);
                    mma16816(sc[2 * i],     qh[kk], &bh[0]);
                    mma16816(sc[2 * i],     qh[kk], &bl[0]);
                    mma16816(sc[2 * i],     ql[kk], &bh[0]);
                    mma16816(sc[2 * i + 1], qh[kk], &bh[2]);
                    mma16816(sc[2 * i + 1], qh[kk], &bl[2]);
                    mma16816(sc[2 * i + 1], ql[kk], &bh[2]);
                }
        }

        const bool diag = (kb >= q0);
        float nm0 = m0, nm1 = m1;
#pragma unroll
        for (int nt = 0; nt < 8; nt++) {
            const int colb = kb + nt * 8 + 2 * tig;
            float t0 = sc[nt][0] * SCL, t1 = sc[nt][1] * SCL;
            float t2 = sc[nt][2] * SCL, t3 = sc[nt][3] * SCL;
            if (diag) {
                if (colb     > row0) t0 = -1e30f;
                if (colb + 1 > row0) t1 = -1e30f;
                if (colb     > row1) t2 = -1e30f;
                if (colb + 1 > row1) t3 = -1e30f;
            }
            sc[nt][0] = t0; sc[nt][1] = t1; sc[nt][2] = t2; sc[nt][3] = t3;
            nm0 = fmaxf(nm0, fmaxf(t0, t1));
            nm1 = fmaxf(nm1, fmaxf(t2, t3));
        }
        nm0 = fmaxf(nm0, __shfl_xor_sync(0xffffffffu, nm0, 1));
        nm0 = fmaxf(nm0, __shfl_xor_sync(0xffffffffu, nm0, 2));
        nm1 = fmaxf(nm1, __shfl_xor_sync(0xffffffffu, nm1, 1));
        nm1 = fmaxf(nm1, __shfl_xor_sync(0xffffffffu, nm1, 2));
        const float c0 = ex2(m0 - nm0), c1 = ex2(m1 - nm1);
        m0 = nm0; m1 = nm1;
        l0 *= c0; l1 *= c1;
#pragma unroll
        for (int nt = 0; nt < 8; nt++) {
            acc_o[nt][0] *= c0; acc_o[nt][1] *= c0;
            acc_o[nt][2] *= c1; acc_o[nt][3] *= c1;
        }
#pragma unroll
        for (int nt = 0; nt < 8; nt++) {
            const float p0 = ex2(sc[nt][0] - m0), p1 = ex2(sc[nt][1] - m0);
            const float p2 = ex2(sc[nt][2] - m1), p3 = ex2(sc[nt][3] - m1);
            l0 += p0 + p1; l1 += p2 + p3;
            sc[nt][0] = p0; sc[nt][1] = p1; sc[nt][2] = p2; sc[nt][3] = p3;
        }

        {
            const int rbase = ((lane >> 3) & 1) * 8 + (lane & 7);
            const int chb = lane >> 4;
#pragma unroll
            for (int kc = 0; kc < 4; kc++) {
                uint32_t aH[4], aL[4];
                pack2(sc[2 * kc][0],     sc[2 * kc][1],     aH[0], aL[0]);
                pack2(sc[2 * kc][2],     sc[2 * kc][3],     aH[1], aL[1]);
                pack2(sc[2 * kc + 1][0], sc[2 * kc + 1][1], aH[2], aL[2]);
                pack2(sc[2 * kc + 1][2], sc[2 * kc + 1][3], aH[3], aL[3]);
                const int r = kc * 16 + rbase;
#pragma unroll
                for (int j = 0; j < 4; j++) {
                    const int ch = 2 * j + chb;
                    const uint32_t off = r * 128 + ((ch ^ (r & 7)) << 4);
                    uint32_t vh[4], vl[4];
                    ldsm_x4_t(vh, so + 16384 + off);
                    ldsm_x4_t(vl, so + 24576 + off);
                    mma16816(acc_o[2 * j],     aH, &vh[0]);
                    mma16816(acc_o[2 * j],     aH, &vl[0]);
                    mma16816(acc_o[2 * j],     aL, &vh[0]);
                    mma16816(acc_o[2 * j + 1], aH, &vh[2]);
                    mma16816(acc_o[2 * j + 1], aH, &vl[2]);
                    mma16816(acc_o[2 * j + 1], aL, &vh[2]);
                }
            }
        }
        __syncthreads();
    }

    l0 += __shfl_xor_sync(0xffffffffu, l0, 1);
    l0 += __shfl_xor_sync(0xffffffffu, l0, 2);
    l1 += __shfl_xor_sync(0xffffffffu, l1, 1);
    l1 += __shfl_xor_sync(0xffffffffu, l1, 2);
    const float i0 = 1.f / l0, i1 = 1.f / l1;
    const size_t b0 = (size_t)row0 * D + h * HD;
    const size_t b1 = (size_t)row1 * D + h * HD;
#pragma unroll
    for (int nt = 0; nt < 8; nt++) {
        const int co = nt * 8 + 2 * tig;
        uint32_t hi, lo;
        pack2(acc_o[nt][0] * i0, acc_o[nt][1] * i0, hi, lo);
        *(uint32_t*)(Ohi + b0 + co) = hi;
        *(uint32_t*)(Olo + b0 + co) = lo;
        pack2(acc_o[nt][2] * i1, acc_o[nt][3] * i1, hi, lo);
        *(uint32_t*)(Ohi + b1 + co) = hi;
        *(uint32_t*)(Olo + b1 + co) = lo;
    }
}

// ---------------------------------------------------------------------------
// Launcher — attention is launch #3 (0-indexed) => ncu capture slot.
// ---------------------------------------------------------------------------
extern "C" void kernel_launch(void* const* d_in, const int* in_sizes, int n_in,
                              void* d_out, int out_size)
{
    const float* x    = (const float*)d_in[0];
    const float* cosT = (const float*)d_in[1];
    const float* sinT = (const float*)d_in[2];
    const float* gq   = (const float*)d_in[3];
    const float* gk   = (const float*)d_in[4];
    const float* Wq   = (const float*)d_in[5];
    const float* Wk   = (const float*)d_in[6];
    const float* Wv   = (const float*)d_in[7];
    const float* Wo   = (const float*)d_in[8];
    float* out = (float*)d_out;

    __nv_bfloat16 *Ahi, *Alo, *KVhi, *KVlo, *Ohi, *Olo;
    __nv_bfloat16 *WqkvTh, *WqkvTl, *WoTh, *WoTl;
    cudaGetSymbolAddress((void**)&Ahi,    g_Ahi);
    cudaGetSymbolAddress((void**)&Alo,    g_Alo);
    cudaGetSymbolAddress((void**)&KVhi,   g_KVhi);
    cudaGetSymbolAddress((void**)&KVlo,   g_KVlo);
    cudaGetSymbolAddress((void**)&Ohi,    g_Ohi);
    cudaGetSymbolAddress((void**)&Olo,    g_Olo);
    cudaGetSymbolAddress((void**)&WqkvTh, g_WqkvThi);
    cudaGetSymbolAddress((void**)&WqkvTl, g_WqkvTlo);
    cudaGetSymbolAddress((void**)&WoTh,   g_WoThi);
    cudaGetSymbolAddress((void**)&WoTl,   g_WoTlo);

    cudaFuncSetAttribute(gemm_mma<0>, cudaFuncAttributeMaxDynamicSharedMemorySize, SMEM_GEMM);
    cudaFuncSetAttribute(gemm_mma<1>, cudaFuncAttributeMaxDynamicSharedMemorySize, SMEM_GEMM);
    cudaFuncSetAttribute(attn_tc,     cudaFuncAttributeMaxDynamicSharedMemorySize, SMEM_ATTN);

    // #0: x split
    cvt_hilo<<<(S * D / 4 + 255) / 256, 256>>>(x, Ahi, Alo, S * D);
    // #1: merged Wq|Wk|Wv transpose+split
    cvt_hilo_T_qkv<<<dim3(DQKV / 32, D / 32), dim3(32, 8)>>>(Wq, Wk, Wv, WqkvTh, WqkvTl);

    // #2: fused QKV projection + RMSNorm + RoPE + hi/lo epilogue.
    gemm_mma<1><<<dim3(DQKV / 128, S / 128), 256, SMEM_GEMM>>>(
        Ahi, Alo, WqkvTh, WqkvTl, nullptr,
        Ohi, Olo, KVhi, KVlo, cosT, sinT, gq, gk, DQKV, D);

    // #3: attention (ncu capture slot). 1024 CTAs, 2 per SM.
    attn_tc<<<dim3(S / ATQ, NQ), 128, SMEM_ATTN>>>(Ohi, Olo, KVhi, KVlo, Ahi, Alo);

    // #4: Wo transpose+split
    cvt_hilo_T<<<dim3(D / 32, D / 32), dim3(32, 8)>>>(Wo, WoTh, WoTl, D, D);

    // #5: output projection (plain fp32 epilogue)
    gemm_mma<0><<<dim3(D / 128, S / 128), 256, SMEM_GEMM>>>(
        Ahi, Alo, WoTh, WoTl, out,
        nullptr, nullptr, nullptr, nullptr, nullptr, nullptr, nullptr, nullptr, D, D);
}

// round 15
// speedup vs baseline: 1.0939x; 1.0185x over previous
#include <cuda_runtime.h>
#include <cuda_bf16.h>
#include <math_constants.h>
#include <cstdint>

// ---------------------------------------------------------------------------
// Problem constants
// ---------------------------------------------------------------------------
#define S    2048
#define D    2048
#define NQ   32
#define NKV  8
#define HD   64
#define DKV  (NKV * HD)    // 512
#define KVS  (2 * DKV)     // 1024: packed K|V row stride
#define DQKV (D + KVS)     // 3072: packed Q|K|V projection width

// ---------------------------------------------------------------------------
// Scratch (device globals: no allocation allowed)
// ---------------------------------------------------------------------------
__device__ __nv_bfloat16 g_Ahi[S * D], g_Alo[S * D];            // x hi/lo -> attn out
__device__ __nv_bfloat16 g_KVhi[S * KVS], g_KVlo[S * KVS];      // K|V hi/lo (post norm)
__device__ __nv_bfloat16 g_Ohi[S * D], g_Olo[S * D];            // Q hi/lo (post norm/rope)
__device__ __nv_bfloat16 g_WqkvThi[DQKV * D], g_WqkvTlo[DQKV * D]; // [Wq;Wk;Wv]^T
__device__ __nv_bfloat16 g_WoThi[D * D], g_WoTlo[D * D];        // Wo^T

// ---------------------------------------------------------------------------
// PTX helpers (base ISA only)
// ---------------------------------------------------------------------------
__device__ __forceinline__ uint32_t smem_u32(const void* p) {
    uint32_t a;
    asm("{ .reg .u64 t; cvta.to.shared.u64 t, %1; cvt.u32.u64 %0, t; }" : "=r"(a) : "l"(p));
    return a;
}
__device__ __forceinline__ void cp_async16(uint32_t dst, const void* src) {
    asm volatile("cp.async.cg.shared.global [%0], [%1], 16;" :: "r"(dst), "l"(src));
}
__device__ __forceinline__ void cp_commit() {
    asm volatile("cp.async.commit_group;" ::: "memory");
}
__device__ __forceinline__ void cp_wait2() {
    asm volatile("cp.async.wait_group 2;" ::: "memory");
}
__device__ __forceinline__ void cp_wait1() {
    asm volatile("cp.async.wait_group 1;" ::: "memory");
}
__device__ __forceinline__ void cp_wait0() {
    asm volatile("cp.async.wait_group 0;" ::: "memory");
}
__device__ __forceinline__ void ldsm_x4(uint32_t* r, uint32_t addr) {
    asm volatile("ldmatrix.sync.aligned.m8n8.x4.shared.b16 {%0,%1,%2,%3}, [%4];"
                 : "=r"(r[0]), "=r"(r[1]), "=r"(r[2]), "=r"(r[3]) : "r"(addr));
}
__device__ __forceinline__ void ldsm_x4_t(uint32_t* r, uint32_t addr) {
    asm volatile("ldmatrix.sync.aligned.m8n8.x4.trans.shared.b16 {%0,%1,%2,%3}, [%4];"
                 : "=r"(r[0]), "=r"(r[1]), "=r"(r[2]), "=r"(r[3]) : "r"(addr));
}
__device__ __forceinline__ void mma16816(float* c, const uint32_t* a, const uint32_t* b) {
    asm volatile(
        "mma.sync.aligned.m16n8k16.row.col.f32.bf16.bf16.f32 "
        "{%0,%1,%2,%3}, {%4,%5,%6,%7}, {%8,%9}, {%0,%1,%2,%3};"
        : "+f"(c[0]), "+f"(c[1]), "+f"(c[2]), "+f"(c[3])
        : "r"(a[0]), "r"(a[1]), "r"(a[2]), "r"(a[3]), "r"(b[0]), "r"(b[1]));
}
__device__ __forceinline__ float ex2(float x) {
    float y;
    asm("ex2.approx.f32 %0, %1;" : "=f"(y) : "f"(x));
    return y;
}
__device__ __forceinline__ uint32_t prmt7632(uint32_t a, uint32_t b) {
    uint32_t r;
    asm("prmt.b32 %0, %1, %2, 0x7632;" : "=r"(r) : "r"(a), "r"(b));
    return r;
}
// RZ-truncation hi/lo split: hi digit = top 16 bits (exact bf16), residual rn.
// ~6 instr vs ~10 for the RN version; split error 2^-17 (vs 2^-18) — fine.
__device__ __forceinline__ void pack2(float x, float y, uint32_t& hi, uint32_t& lo) {
    const uint32_t xb = __float_as_uint(x) & 0xffff0000u;
    const uint32_t yb = __float_as_uint(y) & 0xffff0000u;
    hi = prmt7632(xb, yb);
    __nv_bfloat162 ll = __floats2bfloat162_rn(x - __uint_as_float(xb),
                                              y - __uint_as_float(yb));
    lo = *reinterpret_cast<uint32_t*>(&ll);
}

// ---------------------------------------------------------------------------
// Split-fp32 conversion kernels (input x + weights) — RN split (mem-bound)
// ---------------------------------------------------------------------------
__global__ void cvt_hilo(const float* __restrict__ src,
                         __nv_bfloat16* __restrict__ hi,
                         __nv_bfloat16* __restrict__ lo, int n)
{
    int i = (blockIdx.x * blockDim.x + threadIdx.x) * 4;
    if (i >= n) return;
    float4 v = *(const float4*)(src + i);
    __nv_bfloat16 h0 = __float2bfloat16(v.x), h1 = __float2bfloat16(v.y);
    __nv_bfloat16 h2 = __float2bfloat16(v.z), h3 = __float2bfloat16(v.w);
    __nv_bfloat16 l0 = __float2bfloat16(v.x - __bfloat162float(h0));
    __nv_bfloat16 l1 = __float2bfloat16(v.y - __bfloat162float(h1));
    __nv_bfloat16 l2 = __float2bfloat16(v.z - __bfloat162float(h2));
    __nv_bfloat16 l3 = __float2bfloat16(v.w - __bfloat162float(h3));
    *(__nv_bfloat162*)(hi + i)     = __halves2bfloat162(h0, h1);
    *(__nv_bfloat162*)(hi + i + 2) = __halves2bfloat162(h2, h3);
    *(__nv_bfloat162*)(lo + i)     = __halves2bfloat162(l0, l1);
    *(__nv_bfloat162*)(lo + i + 2) = __halves2bfloat162(l2, l3);
}

// Merged transpose+split for packed [Wq;Wk;Wv]^T.
__global__ void cvt_hilo_T_qkv(const float* __restrict__ Wq,
                               const float* __restrict__ Wk,
                               const float* __restrict__ Wv,
                               __nv_bfloat16* __restrict__ hiT,
                               __nv_bfloat16* __restrict__ loT)
{
    __shared__ float t[32][33];
    const int k0 = blockIdx.y * 32, n0 = blockIdx.x * 32;
    const int tx = threadIdx.x, ty = threadIdx.y;

    const float* src;
    int nn, Ns;
    if (n0 < D)            { src = Wq; nn = n0;            Ns = D;   }
    else if (n0 < D + DKV) { src = Wk; nn = n0 - D;        Ns = DKV; }
    else                   { src = Wv; nn = n0 - D - DKV;  Ns = DKV; }

#pragma unroll
    for (int i = 0; i < 4; i++)
        t[ty + i * 8][tx] = src[(size_t)(k0 + ty + i * 8) * Ns + nn + tx];
    __syncthreads();
#pragma unroll
    for (int i = 0; i < 4; i++) {
        const int r = ty + i * 8;
        float v = t[tx][r];
        __nv_bfloat16 h = __float2bfloat16(v);
        __nv_bfloat16 l = __float2bfloat16(v - __bfloat162float(h));
        hiT[(size_t)(n0 + r) * D + k0 + tx] = h;
        loT[(size_t)(n0 + r) * D + k0 + tx] = l;
    }
}

// W[K,N] row-major -> WT_hi/lo[N,K] (Wo only)
__global__ void cvt_hilo_T(const float* __restrict__ W,
                           __nv_bfloat16* __restrict__ hiT,
                           __nv_bfloat16* __restrict__ loT, int K, int N)
{
    __shared__ float t[32][33];
    const int k0 = blockIdx.y * 32, n0 = blockIdx.x * 32;
    const int tx = threadIdx.x, ty = threadIdx.y;
#pragma unroll
    for (int i = 0; i < 4; i++)
        t[ty + i * 8][tx] = W[(size_t)(k0 + ty + i * 8) * N + n0 + tx];
    __syncthreads();
#pragma unroll
    for (int i = 0; i < 4; i++) {
        const int r = ty + i * 8;
        float v = t[tx][r];
        __nv_bfloat16 h = __float2bfloat16(v);
        __nv_bfloat16 l = __float2bfloat16(v - __bfloat162float(h));
        hiT[(size_t)(n0 + r) * K + k0 + tx] = h;
        loT[(size_t)(n0 + r) * K + k0 + tx] = l;
    }
}

// ---------------------------------------------------------------------------
// bf16x3 GEMM — 128x128 CTA tile, BK=64, 3-stage pipeline, 256 threads,
// 8 warps in 4(m) x 2(n): warp tile 32 rows x 64 cols.
// FUSED=0: plain fp32 C store (Wo). FUSED=1: RMSNorm+RoPE+hi/lo epilogue;
//          Q additionally pre-scaled by 1/8*log2(e) for the attention softmax.
// ---------------------------------------------------------------------------
#define BK 64
#define TILE_B (128 * 128)
#define STAGE_B (4 * TILE_B)                 // 64 KB
#define NSTAGE 3
#define SMEM_GEMM (NSTAGE * STAGE_B + 128)   // ~192 KB

template<int FUSED>
__global__ __launch_bounds__(256, 1) void gemm_mma(
    const __nv_bfloat16* __restrict__ Ahi, const __nv_bfloat16* __restrict__ Alo,
    const __nv_bfloat16* __restrict__ Bhi, const __nv_bfloat16* __restrict__ Blo,
    float* __restrict__ C,
    __nv_bfloat16* __restrict__ QHi, __nv_bfloat16* __restrict__ QLo,
    __nv_bfloat16* __restrict__ KVHi, __nv_bfloat16* __restrict__ KVLo,
    const float* __restrict__ cosT, const float* __restrict__ sinT,
    const float* __restrict__ gq, const float* __restrict__ gk,
    int N, int K)
{
    extern __shared__ char smem_raw[];
    uint32_t sb = (smem_u32(smem_raw) + 127) & ~127u;

    const int tid  = threadIdx.x;
    const int wid  = tid >> 5;
    const int lane = tid & 31;
    const int wm   = wid >> 1;
    const int wn   = wid & 1;
    const int m0   = blockIdx.y * 128;
    const int n0   = blockIdx.x * 128;

    const __nv_bfloat16* srcs[4] = {
        Ahi + (size_t)m0 * K, Alo + (size_t)m0 * K,
        Bhi + (size_t)n0 * K, Blo + (size_t)n0 * K };

    const int NK = K / BK;

    auto issue_stage = [&](int ks, int st) {
        const int k0 = ks * BK;
        const uint32_t so = sb + st * STAGE_B;
#pragma unroll
        for (int mat = 0; mat < 4; mat++) {
            const __nv_bfloat16* bp = srcs[mat] + k0;
#pragma unroll
            for (int j = 0; j < 4; j++) {
                const int idx = j * 256 + tid;
                const int r   = idx >> 3;
                const int ch  = idx & 7;
                const uint32_t dst = so + mat * TILE_B + r * 128 + ((ch ^ (r & 7)) << 4);
                cp_async16(dst, bp + (size_t)r * K + ch * 8);
            }
        }
    };

    issue_stage(0, 0); cp_commit();
    issue_stage(1, 1); cp_commit();
    issue_stage(2, 2); cp_commit();

    float acc[2][8][4];
#pragma unroll
    for (int i = 0; i < 2; i++)
#pragma unroll
        for (int j = 0; j < 8; j++)
#pragma unroll
            for (int k = 0; k < 4; k++) acc[i][j][k] = 0.f;

    const int rA = wm * 32 + ((lane >> 3) & 1) * 8 + (lane & 7);
    const int cA = lane >> 4;
    const int rB = wn * 64 + (lane >> 4) * 8 + (lane & 7);
    const int cB = (lane >> 3) & 1;

    int st = 0;
    for (int ks = 0; ks < NK; ks++) {
        const uint32_t so = sb + st * STAGE_B;
        cp_wait2();
        __syncthreads();

        const uint32_t tAh = so;
        const uint32_t tAl = so + TILE_B;
        const uint32_t tBh = so + 2 * TILE_B;
        const uint32_t tBl = so + 3 * TILE_B;

#pragma unroll
        for (int kk = 0; kk < 4; kk++) {
            uint32_t ah[2][4], al[2][4], bh[16], bl[16];
#pragma unroll
            for (int mt = 0; mt < 2; mt++) {
                const int r = rA + mt * 16;
                const int ch = kk * 2 + cA;
                const uint32_t off = r * 128 + ((ch ^ (r & 7)) << 4);
                ldsm_x4(ah[mt], tAh + off);
                ldsm_x4(al[mt], tAl + off);
            }
#pragma unroll
            for (int p = 0; p < 4; p++) {
                const int r = rB + p * 16;
                const int ch = kk * 2 + cB;
                const uint32_t off = r * 128 + ((ch ^ (r & 7)) << 4);
                ldsm_x4(&bh[p * 4], tBh + off);
                ldsm_x4(&bl[p * 4], tBl + off);
            }
#pragma unroll
            for (int mt = 0; mt < 2; mt++)
#pragma unroll
                for (int nt = 0; nt < 8; nt++)
                    mma16816(acc[mt][nt], ah[mt], &bh[nt * 2]);
#pragma unroll
            for (int mt = 0; mt < 2; mt++)
#pragma unroll
                for (int nt = 0; nt < 8; nt++)
                    mma16816(acc[mt][nt], ah[mt], &bl[nt * 2]);
#pragma unroll
            for (int mt = 0; mt < 2; mt++)
#pragma unroll
                for (int nt = 0; nt < 8; nt++)
                    mma16816(acc[mt][nt], al[mt], &bh[nt * 2]);
        }
        __syncthreads();
        if (ks + NSTAGE < NK) issue_stage(ks + NSTAGE, st);
        cp_commit();
        st = (st + 1 == NSTAGE) ? 0 : st + 1;
    }

    const int cr  = lane >> 2;
    const int tig = lane & 3;
    const int cc  = tig * 2;

    if (FUSED == 0) {
#pragma unroll
        for (int mt = 0; mt < 2; mt++) {
            const int rowb = m0 + wm * 32 + mt * 16 + cr;
#pragma unroll
            for (int nt = 0; nt < 8; nt++) {
                const int col = n0 + wn * 64 + nt * 8 + cc;
                *(float2*)(C + (size_t)rowb * N + col) =
                    make_float2(acc[mt][nt][0], acc[mt][nt][1]);
                *(float2*)(C + (size_t)(rowb + 8) * N + col) =
                    make_float2(acc[mt][nt][2], acc[mt][nt][3]);
            }
        }
    } else {
        const int bx = blockIdx.x;
        const bool isQ = (bx < 16);
        const bool donorm = (bx < 20);
        __nv_bfloat16* Hi = isQ ? QHi : KVHi;
        __nv_bfloat16* Lo = isQ ? QLo : KVLo;
        const int ostride = isQ ? D : KVS;
        const int colbase = (isQ ? n0 : n0 - D) + wn * 64;
        const float* g = isQ ? gq : gk;
        // softmax scale folded into Q only
        const float qscl = isQ ? (0.125f * 1.44269504088896f) : 1.f;

#pragma unroll
        for (int mt = 0; mt < 2; mt++) {
#pragma unroll
            for (int half = 0; half < 2; half++) {
                const int k0 = half * 2;
                const int row = m0 + wm * 32 + mt * 16 + cr + half * 8;
                if (donorm) {
                    float ss = 0.f;
#pragma unroll
                    for (int nt = 0; nt < 8; nt++)
                        ss += acc[mt][nt][k0] * acc[mt][nt][k0]
                            + acc[mt][nt][k0 + 1] * acc[mt][nt][k0 + 1];
                    ss += __shfl_xor_sync(0xffffffffu, ss, 1);
                    ss += __shfl_xor_sync(0xffffffffu, ss, 2);
                    const float rr = rsqrtf(ss * (1.f / 64.f) + 1e-6f) * qscl;
#pragma unroll
                    for (int nt = 0; nt < 4; nt++) {
                        const int d0 = nt * 8 + cc;
                        const float x1a = acc[mt][nt][k0]     * rr * g[d0];
                        const float x1b = acc[mt][nt][k0 + 1] * rr * g[d0 + 1];
                        const float x2a = acc[mt][nt + 4][k0]     * rr * g[d0 + 32];
                        const float x2b = acc[mt][nt + 4][k0 + 1] * rr * g[d0 + 33];
                        const float ca = cosT[row * 32 + d0];
                        const float cb = cosT[row * 32 + d0 + 1];
                        const float sa = sinT[row * 32 + d0];
                        const float sbn = sinT[row * 32 + d0 + 1];
                        uint32_t h, l;
                        pack2(x1a * ca - x2a * sa, x1b * cb - x2b * sbn, h, l);
                        *(uint32_t*)(Hi + (size_t)row * ostride + colbase + d0) = h;
                        *(uint32_t*)(Lo + (size_t)row * ostride + colbase + d0) = l;
                        pack2(x1a * sa + x2a * ca, x1b * sbn + x2b * cb, h, l);
                        *(uint32_t*)(Hi + (size_t)row * ostride + colbase + d0 + 32) = h;
                        *(uint32_t*)(Lo + (size_t)row * ostride + colbase + d0 + 32) = l;
                    }
                } else {
#pragma unroll
                    for (int nt = 0; nt < 8; nt++) {
                        uint32_t h, l;
                        pack2(acc[mt][nt][k0], acc[mt][nt][k0 + 1], h, l);
                        const int col = colbase + nt * 8 + cc;
                        *(uint32_t*)(Hi + (size_t)row * ostride + col) = h;
                        *(uint32_t*)(Lo + (size_t)row * ostride + col) = l;
                    }
                }
            }
        }
    }
}

// ---------------------------------------------------------------------------
// Tensor-core causal GQA flash attention (bf16x3, fp32 softmax).
// ATQ=64, 128 threads (4 warps), 2-stage KV pipeline, 2 CTAs/SM.
// Q pre-scaled by 1/8*log2(e); ex2.approx; hoisted mask branch; PRMT pack2.
// ---------------------------------------------------------------------------
#define ATQ 64
#define ATK 64
#define AQL_OFF   8192
#define ASTG_OFF  16384
#define ASTG_SZ   32768
#define SMEM_ATTN (ASTG_OFF + 2 * ASTG_SZ + 128)   // ~80KB -> 2 CTAs/SM

__global__ __launch_bounds__(128, 2) void attn_tc(
    const __nv_bfloat16* __restrict__ Qhi, const __nv_bfloat16* __restrict__ Qlo,
    const __nv_bfloat16* __restrict__ KVhi, const __nv_bfloat16* __restrict__ KVlo,
    __nv_bfloat16* __restrict__ Ohi, __nv_bfloat16* __restrict__ Olo)
{
    extern __shared__ char smem_raw[];
    const uint32_t sb = (smem_u32(smem_raw) + 127) & ~127u;
    const int tid = threadIdx.x, wid = tid >> 5, lane = tid & 31;
    const int h = blockIdx.y, hk = h >> 2;
    const int qb = gridDim.x - 1 - blockIdx.x;       // heavy blocks first
    const int q0 = qb * ATQ;
    const int g = lane >> 2, tig = lane & 3;

    const int ntile = (q0 + ATQ) / ATK;              // qb + 1

    auto issue_kv = [&](int t, int st) {
        const int kb = t * ATK;
        const uint32_t so = sb + ASTG_OFF + st * ASTG_SZ;
        const __nv_bfloat16* bases[4] = {
            KVhi + (size_t)kb * KVS + hk * HD,
            KVlo + (size_t)kb * KVS + hk * HD,
            KVhi + (size_t)kb * KVS + DKV + hk * HD,
            KVlo + (size_t)kb * KVS + DKV + hk * HD };
#pragma unroll
        for (int mat = 0; mat < 4; mat++)
#pragma unroll
            for (int j = 0; j < 4; j++) {
                const int idx = j * 128 + tid;        // 0..511
                const int r = idx >> 3, ch = idx & 7;
                const uint32_t dst = so + mat * 8192 + r * 128 + ((ch ^ (r & 7)) << 4);
                cp_async16(dst, bases[mat] + (size_t)r * KVS + ch * 8);
            }
    };

    // prologue: Q (64 rows x 128B, hi+lo)
    {
        const __nv_bfloat16* qsrc[2] = { Qhi + (size_t)q0 * D + h * HD,
                                         Qlo + (size_t)q0 * D + h * HD };
#pragma unroll
        for (int mat = 0; mat < 2; mat++)
#pragma unroll
            for (int j = 0; j < 4; j++) {
                const int idx = j * 128 + tid;
                const int r = idx >> 3, ch = idx & 7;
                const uint32_t dst = sb + mat * AQL_OFF + r * 128 + ((ch ^ (r & 7)) << 4);
                cp_async16(dst, qsrc[mat] + (size_t)r * D + ch * 8);
            }
    }
    cp_commit();
    issue_kv(0, 0); cp_commit();

    cp_wait1();          // Q done (kv0 may be in flight)
    __syncthreads();

    uint32_t qh[4][4], ql[4][4];
    {
        const int r = wid * 16 + (lane & 15);         // rows 0..63
        const int chb = lane >> 4;
#pragma unroll
        for (int kk = 0; kk < 4; kk++) {
            const int ch = kk * 2 + chb;
            const uint32_t off = r * 128 + ((ch ^ (r & 7)) << 4);
            ldsm_x4(qh[kk], sb + off);
            ldsm_x4(ql[kk], sb + AQL_OFF + off);
        }
    }

    float acc_o[8][4];
#pragma unroll
    for (int i = 0; i < 8; i++)
#pragma unroll
        for (int j = 0; j < 4; j++) acc_o[i][j] = 0.f;
    float m0 = -1e30f, m1 = -1e30f, l0 = 0.f, l1 = 0.f;

    const int row0 = q0 + wid * 16 + g;
    const int row1 = row0 + 8;

    for (int t = 0; t < ntile; t++) {
        if (t + 1 < ntile) { issue_kv(t + 1, (t + 1) & 1); cp_commit(); cp_wait1(); }
        else cp_wait0();
        __syncthreads();

        const uint32_t so = sb + ASTG_OFF + (t & 1) * ASTG_SZ;
        const int kb = t * ATK;

        float sc[8][4];
#pragma unroll
        for (int i = 0; i < 8; i++)
#pragma unroll
            for (int j = 0; j < 4; j++) sc[i][j] = 0.f;

        {
            const int rbase = ((lane >> 4) & 1) * 8 + (lane & 7);
            const int chb = (lane >> 3) & 1;
#pragma unroll
            for (int kk = 0; kk < 4; kk++)
#pragma unroll
                for (int i = 0; i < 4; i++) {
                    const int r = i * 16 + rbase;
                    const int ch = kk * 2 + chb;
                    const uint32_t off = r * 128 + ((ch ^ (r & 7)) << 4);
                    uint32_t bh[4], bl[4];
                    ldsm_x4(bh, so + off);
                    ldsm_x4(bl, so + 8192 + off);
                    mma16816(sc[2 * i],     qh[kk], &bh[0]);
                    mma16816(sc[2 * i],     qh[kk], &bl[0]);
                    mma16816(sc[2 * i],     ql[kk], &bh[0]);
                    mma16816(sc[2 * i + 1], qh[kk], &bh[2]);
                    mma16816(sc[2 * i + 1], qh[kk], &bl[2]);
                    mma16816(sc[2 * i + 1], ql[kk], &bh[2]);
                }
        }

        // scores already scaled (Q pre-scaled by 1/8*log2 e)
        float nm0 = m0, nm1 = m1;
        if (kb >= q0) {           // diagonal tile: apply causal mask
#pragma unroll
            for (int nt = 0; nt < 8; nt++) {
                const int colb = kb + nt * 8 + 2 * tig;
                if (colb     > row0) sc[nt][0] = -1e30f;
                if (colb + 1 > row0) sc[nt][1] = -1e30f;
                if (colb     > row1) sc[nt][2] = -1e30f;
                if (colb + 1 > row1) sc[nt][3] = -1e30f;
                nm0 = fmaxf(nm0, fmaxf(sc[nt][0], sc[nt][1]));
                nm1 = fmaxf(nm1, fmaxf(sc[nt][2], sc[nt][3]));
            }
        } else {
#pragma unroll
            for (int nt = 0; nt < 8; nt++) {
                nm0 = fmaxf(nm0, fmaxf(sc[nt][0], sc[nt][1]));
                nm1 = fmaxf(nm1, fmaxf(sc[nt][2], sc[nt][3]));
            }
        }
        nm0 = fmaxf(nm0, __shfl_xor_sync(0xffffffffu, nm0, 1));
        nm0 = fmaxf(nm0, __shfl_xor_sync(0xffffffffu, nm0, 2));
        nm1 = fmaxf(nm1, __shfl_xor_sync(0xffffffffu, nm1, 1));
        nm1 = fmaxf(nm1, __shfl_xor_sync(0xffffffffu, nm1, 2));
        const float c0 = ex2(m0 - nm0), c1 = ex2(m1 - nm1);
        m0 = nm0; m1 = nm1;
        l0 *= c0; l1 *= c1;
#pragma unroll
        for (int nt = 0; nt < 8; nt++) {
            acc_o[nt][0] *= c0; acc_o[nt][1] *= c0;
            acc_o[nt][2] *= c1; acc_o[nt][3] *= c1;
        }
#pragma unroll
        for (int nt = 0; nt < 8; nt++) {
            const float p0 = ex2(sc[nt][0] - m0), p1 = ex2(sc[nt][1] - m0);
            const float p2 = ex2(sc[nt][2] - m1), p3 = ex2(sc[nt][3] - m1);
            l0 += p0 + p1; l1 += p2 + p3;
            sc[nt][0] = p0; sc[nt][1] = p1; sc[nt][2] = p2; sc[nt][3] = p3;
        }

        {
            const int rbase = ((lane >> 3) & 1) * 8 + (lane & 7);
            const int chb = lane >> 4;
#pragma unroll
            for (int kc = 0; kc < 4; kc++) {
                uint32_t aH[4], aL[4];
                pack2(sc[2 * kc][0],     sc[2 * kc][1],     aH[0], aL[0]);
                pack2(sc[2 * kc][2],     sc[2 * kc][3],     aH[1], aL[1]);
                pack2(sc[2 * kc + 1][0], sc[2 * kc + 1][1], aH[2], aL[2]);
                pack2(sc[2 * kc + 1][2], sc[2 * kc + 1][3], aH[3], aL[3]);
                const int r = kc * 16 + rbase;
#pragma unroll
                for (int j = 0; j < 4; j++) {
                    const int ch = 2 * j + chb;
                    const uint32_t off = r * 128 + ((ch ^ (r & 7)) << 4);
                    uint32_t vh[4], vl[4];
                    ldsm_x4_t(vh, so + 16384 + off);
                    ldsm_x4_t(vl, so + 24576 + off);
                    mma16816(acc_o[2 * j],     aH, &vh[0]);
                    mma16816(acc_o[2 * j],     aH, &vl[0]);
                    mma16816(acc_o[2 * j],     aL, &vh[0]);
                    mma16816(acc_o[2 * j + 1], aH, &vh[2]);
                    mma16816(acc_o[2 * j + 1], aH, &vl[2]);
                    mma16816(acc_o[2 * j + 1], aL, &vh[2]);
                }
            }
        }
        __syncthreads();
    }

    l0 += __shfl_xor_sync(0xffffffffu, l0, 1);
    l0 += __shfl_xor_sync(0xffffffffu, l0, 2);
    l1 += __shfl_xor_sync(0xffffffffu, l1, 1);
    l1 += __shfl_xor_sync(0xffffffffu, l1, 2);
    const float i0 = 1.f / l0, i1 = 1.f / l1;
    const size_t b0 = (size_t)row0 * D + h * HD;
    const size_t b1 = (size_t)row1 * D + h * HD;
#pragma unroll
    for (int nt = 0; nt < 8; nt++) {
        const int co = nt * 8 + 2 * tig;
        uint32_t hi, lo;
        pack2(acc_o[nt][0] * i0, acc_o[nt][1] * i0, hi, lo);
        *(uint32_t*)(Ohi + b0 + co) = hi;
        *(uint32_t*)(Olo + b0 + co) = lo;
        pack2(acc_o[nt][2] * i1, acc_o[nt][3] * i1, hi, lo);
        *(uint32_t*)(Ohi + b1 + co) = hi;
        *(uint32_t*)(Olo + b1 + co) = lo;
    }
}

// ---------------------------------------------------------------------------
// Launcher — attention is launch #3 (0-indexed) => ncu capture slot.
// ---------------------------------------------------------------------------
extern "C" void kernel_launch(void* const* d_in, const int* in_sizes, int n_in,
                              void* d_out, int out_size)
{
    const float* x    = (const float*)d_in[0];
    const float* cosT = (const float*)d_in[1];
    const float* sinT = (const float*)d_in[2];
    const float* gq   = (const float*)d_in[3];
    const float* gk   = (const float*)d_in[4];
    const float* Wq   = (const float*)d_in[5];
    const float* Wk   = (const float*)d_in[6];
    const float* Wv   = (const float*)d_in[7];
    const float* Wo   = (const float*)d_in[8];
    float* out = (float*)d_out;

    __nv_bfloat16 *Ahi, *Alo, *KVhi, *KVlo, *Ohi, *Olo;
    __nv_bfloat16 *WqkvTh, *WqkvTl, *WoTh, *WoTl;
    cudaGetSymbolAddress((void**)&Ahi,    g_Ahi);
    cudaGetSymbolAddress((void**)&Alo,    g_Alo);
    cudaGetSymbolAddress((void**)&KVhi,   g_KVhi);
    cudaGetSymbolAddress((void**)&KVlo,   g_KVlo);
    cudaGetSymbolAddress((void**)&Ohi,    g_Ohi);
    cudaGetSymbolAddress((void**)&Olo,    g_Olo);
    cudaGetSymbolAddress((void**)&WqkvTh, g_WqkvThi);
    cudaGetSymbolAddress((void**)&WqkvTl, g_WqkvTlo);
    cudaGetSymbolAddress((void**)&WoTh,   g_WoThi);
    cudaGetSymbolAddress((void**)&WoTl,   g_WoTlo);

    cudaFuncSetAttribute(gemm_mma<0>, cudaFuncAttributeMaxDynamicSharedMemorySize, SMEM_GEMM);
    cudaFuncSetAttribute(gemm_mma<1>, cudaFuncAttributeMaxDynamicSharedMemorySize, SMEM_GEMM);
    cudaFuncSetAttribute(attn_tc,     cudaFuncAttributeMaxDynamicSharedMemorySize, SMEM_ATTN);

    // #0: x split
    cvt_hilo<<<(S * D / 4 + 255) / 256, 256>>>(x, Ahi, Alo, S * D);
    // #1: merged Wq|Wk|Wv transpose+split
    cvt_hilo_T_qkv<<<dim3(DQKV / 32, D / 32), dim3(32, 8)>>>(Wq, Wk, Wv, WqkvTh, WqkvTl);

    // #2: fused QKV projection + RMSNorm + RoPE (+Q softmax prescale) + hi/lo
    gemm_mma<1><<<dim3(DQKV / 128, S / 128), 256, SMEM_GEMM>>>(
        Ahi, Alo, WqkvTh, WqkvTl, nullptr,
        Ohi, Olo, KVhi, KVlo, cosT, sinT, gq, gk, DQKV, D);

    // #3: attention (ncu capture slot). 1024 CTAs, 2 per SM.
    attn_tc<<<dim3(S / ATQ, NQ), 128, SMEM_ATTN>>>(Ohi, Olo, KVhi, KVlo, Ahi, Alo);

    // #4: Wo transpose+split
    cvt_hilo_T<<<dim3(D / 32, D / 32), dim3(32, 8)>>>(Wo, WoTh, WoTl, D, D);

    // #5: output projection (plain fp32 epilogue)
    gemm_mma<0><<<dim3(D / 128, S / 128), 256, SMEM_GEMM>>>(
        Ahi, Alo, WoTh, WoTl, out,
        nullptr, nullptr, nullptr, nullptr, nullptr, nullptr, nullptr, nullptr, D, D);
}

// round 16
// speedup vs baseline: 1.1186x; 1.0225x over previous
#include <cuda_runtime.h>
#include <cuda_bf16.h>
#include <math_constants.h>
#include <cstdint>

// ---------------------------------------------------------------------------
// Problem constants
// ---------------------------------------------------------------------------
#define S    2048
#define D    2048
#define NQ   32
#define NKV  8
#define HD   64
#define DKV  (NKV * HD)    // 512
#define KVS  (2 * DKV)     // 1024: packed K|V row stride
#define DQKV (D + KVS)     // 3072: packed Q|K|V projection width

// ---------------------------------------------------------------------------
// Scratch (device globals: no allocation allowed)
// ---------------------------------------------------------------------------
__device__ __nv_bfloat16 g_Ahi[S * D], g_Alo[S * D];            // x hi/lo -> attn out
__device__ __nv_bfloat16 g_KVhi[S * KVS], g_KVlo[S * KVS];      // K|V hi/lo (post norm)
__device__ __nv_bfloat16 g_Ohi[S * D], g_Olo[S * D];            // Q hi/lo (post norm/rope)
__device__ __nv_bfloat16 g_WqkvThi[DQKV * D], g_WqkvTlo[DQKV * D]; // [Wq;Wk;Wv]^T
__device__ __nv_bfloat16 g_WoThi[D * D], g_WoTlo[D * D];        // Wo^T

// ---------------------------------------------------------------------------
// PTX helpers (base ISA only)
// ---------------------------------------------------------------------------
__device__ __forceinline__ uint32_t smem_u32(const void* p) {
    uint32_t a;
    asm("{ .reg .u64 t; cvta.to.shared.u64 t, %1; cvt.u32.u64 %0, t; }" : "=r"(a) : "l"(p));
    return a;
}
__device__ __forceinline__ void cp_async16(uint32_t dst, const void* src) {
    asm volatile("cp.async.cg.shared.global [%0], [%1], 16;" :: "r"(dst), "l"(src));
}
__device__ __forceinline__ void cp_commit() {
    asm volatile("cp.async.commit_group;" ::: "memory");
}
__device__ __forceinline__ void cp_wait1() {
    asm volatile("cp.async.wait_group 1;" ::: "memory");
}
__device__ __forceinline__ void cp_wait0() {
    asm volatile("cp.async.wait_group 0;" ::: "memory");
}
__device__ __forceinline__ void ldsm_x4(uint32_t* r, uint32_t addr) {
    asm volatile("ldmatrix.sync.aligned.m8n8.x4.shared.b16 {%0,%1,%2,%3}, [%4];"
                 : "=r"(r[0]), "=r"(r[1]), "=r"(r[2]), "=r"(r[3]) : "r"(addr));
}
__device__ __forceinline__ void ldsm_x4_t(uint32_t* r, uint32_t addr) {
    asm volatile("ldmatrix.sync.aligned.m8n8.x4.trans.shared.b16 {%0,%1,%2,%3}, [%4];"
                 : "=r"(r[0]), "=r"(r[1]), "=r"(r[2]), "=r"(r[3]) : "r"(addr));
}
__device__ __forceinline__ void mma16816(float* c, const uint32_t* a, const uint32_t* b) {
    asm volatile(
        "mma.sync.aligned.m16n8k16.row.col.f32.bf16.bf16.f32 "
        "{%0,%1,%2,%3}, {%4,%5,%6,%7}, {%8,%9}, {%0,%1,%2,%3};"
        : "+f"(c[0]), "+f"(c[1]), "+f"(c[2]), "+f"(c[3])
        : "r"(a[0]), "r"(a[1]), "r"(a[2]), "r"(a[3]), "r"(b[0]), "r"(b[1]));
}
__device__ __forceinline__ float ex2(float x) {
    float y;
    asm("ex2.approx.f32 %0, %1;" : "=f"(y) : "f"(x));
    return y;
}
__device__ __forceinline__ uint32_t prmt7632(uint32_t a, uint32_t b) {
    uint32_t r;
    asm("prmt.b32 %0, %1, %2, 0x7632;" : "=r"(r) : "r"(a), "r"(b));
    return r;
}
// RZ-truncation hi/lo split (validated R15).
__device__ __forceinline__ void pack2(float x, float y, uint32_t& hi, uint32_t& lo) {
    const uint32_t xb = __float_as_uint(x) & 0xffff0000u;
    const uint32_t yb = __float_as_uint(y) & 0xffff0000u;
    hi = prmt7632(xb, yb);
    __nv_bfloat162 ll = __floats2bfloat162_rn(x - __uint_as_float(xb),
                                              y - __uint_as_float(yb));
    lo = *reinterpret_cast<uint32_t*>(&ll);
}

// ---------------------------------------------------------------------------
// Split-fp32 conversion kernels (input x + weights)
// ---------------------------------------------------------------------------
__global__ void cvt_hilo(const float* __restrict__ src,
                         __nv_bfloat16* __restrict__ hi,
                         __nv_bfloat16* __restrict__ lo, int n)
{
    int i = (blockIdx.x * blockDim.x + threadIdx.x) * 4;
    if (i >= n) return;
    float4 v = *(const float4*)(src + i);
    __nv_bfloat16 h0 = __float2bfloat16(v.x), h1 = __float2bfloat16(v.y);
    __nv_bfloat16 h2 = __float2bfloat16(v.z), h3 = __float2bfloat16(v.w);
    __nv_bfloat16 l0 = __float2bfloat16(v.x - __bfloat162float(h0));
    __nv_bfloat16 l1 = __float2bfloat16(v.y - __bfloat162float(h1));
    __nv_bfloat16 l2 = __float2bfloat16(v.z - __bfloat162float(h2));
    __nv_bfloat16 l3 = __float2bfloat16(v.w - __bfloat162float(h3));
    *(__nv_bfloat162*)(hi + i)     = __halves2bfloat162(h0, h1);
    *(__nv_bfloat162*)(hi + i + 2) = __halves2bfloat162(h2, h3);
    *(__nv_bfloat162*)(lo + i)     = __halves2bfloat162(l0, l1);
    *(__nv_bfloat162*)(lo + i + 2) = __halves2bfloat162(l2, l3);
}

// Merged transpose+split for packed [Wq;Wk;Wv]^T.
__global__ void cvt_hilo_T_qkv(const float* __restrict__ Wq,
                               const float* __restrict__ Wk,
                               const float* __restrict__ Wv,
                               __nv_bfloat16* __restrict__ hiT,
                               __nv_bfloat16* __restrict__ loT)
{
    __shared__ float t[32][33];
    const int k0 = blockIdx.y * 32, n0 = blockIdx.x * 32;
    const int tx = threadIdx.x, ty = threadIdx.y;

    const float* src;
    int nn, Ns;
    if (n0 < D)            { src = Wq; nn = n0;            Ns = D;   }
    else if (n0 < D + DKV) { src = Wk; nn = n0 - D;        Ns = DKV; }
    else                   { src = Wv; nn = n0 - D - DKV;  Ns = DKV; }

#pragma unroll
    for (int i = 0; i < 4; i++)
        t[ty + i * 8][tx] = src[(size_t)(k0 + ty + i * 8) * Ns + nn + tx];
    __syncthreads();
#pragma unroll
    for (int i = 0; i < 4; i++) {
        const int r = ty + i * 8;
        float v = t[tx][r];
        __nv_bfloat16 h = __float2bfloat16(v);
        __nv_bfloat16 l = __float2bfloat16(v - __bfloat162float(h));
        hiT[(size_t)(n0 + r) * D + k0 + tx] = h;
        loT[(size_t)(n0 + r) * D + k0 + tx] = l;
    }
}

// W[K,N] row-major -> WT_hi/lo[N,K] (Wo only)
__global__ void cvt_hilo_T(const float* __restrict__ W,
                           __nv_bfloat16* __restrict__ hiT,
                           __nv_bfloat16* __restrict__ loT, int K, int N)
{
    __shared__ float t[32][33];
    const int k0 = blockIdx.y * 32, n0 = blockIdx.x * 32;
    const int tx = threadIdx.x, ty = threadIdx.y;
#pragma unroll
    for (int i = 0; i < 4; i++)
        t[ty + i * 8][tx] = W[(size_t)(k0 + ty + i * 8) * N + n0 + tx];
    __syncthreads();
#pragma unroll
    for (int i = 0; i < 4; i++) {
        const int r = ty + i * 8;
        float v = t[tx][r];
        __nv_bfloat16 h = __float2bfloat16(v);
        __nv_bfloat16 l = __float2bfloat16(v - __bfloat162float(h));
        hiT[(size_t)(n0 + r) * K + k0 + tx] = h;
        loT[(size_t)(n0 + r) * K + k0 + tx] = l;
    }
}

// ---------------------------------------------------------------------------
// bf16x3 GEMM — CTA tile 64(m) x 128(n), BK=64, 2-stage pipeline, 128 threads,
// 4 warps in 2(m) x 2(n): warp tile 32x64 (the proven shape). 48 KB/stage,
// 96 KB smem => 2 CTAs per SM for cross-CTA tensor overlap.
// FUSED=0: plain fp32 C store (Wo). FUSED=1: RMSNorm+RoPE+hi/lo epilogue;
//          Q additionally pre-scaled by 1/8*log2(e).
// ---------------------------------------------------------------------------
#define BM 64
#define BK 64
#define A_T_B (BM * 128)                     // 8 KB per A digit tile
#define B_T_B (128 * 128)                    // 16 KB per B digit tile
#define STAGE_B (2 * A_T_B + 2 * B_T_B)      // 48 KB
#define SMEM_GEMM (2 * STAGE_B + 128)        // ~96 KB -> 2 CTAs/SM

template<int FUSED>
__global__ __launch_bounds__(128, 2) void gemm_mma(
    const __nv_bfloat16* __restrict__ Ahi, const __nv_bfloat16* __restrict__ Alo,
    const __nv_bfloat16* __restrict__ Bhi, const __nv_bfloat16* __restrict__ Blo,
    float* __restrict__ C,
    __nv_bfloat16* __restrict__ QHi, __nv_bfloat16* __restrict__ QLo,
    __nv_bfloat16* __restrict__ KVHi, __nv_bfloat16* __restrict__ KVLo,
    const float* __restrict__ cosT, const float* __restrict__ sinT,
    const float* __restrict__ gq, const float* __restrict__ gk,
    int N, int K)
{
    extern __shared__ char smem_raw[];
    uint32_t sb = (smem_u32(smem_raw) + 127) & ~127u;

    const int tid  = threadIdx.x;
    const int wid  = tid >> 5;
    const int lane = tid & 31;
    const int wm   = wid >> 1;          // 0..1 (32 rows each)
    const int wn   = wid & 1;           // 0..1 (64 cols each)
    const int m0   = blockIdx.y * BM;
    const int n0   = blockIdx.x * 128;

    const __nv_bfloat16* srcs[4] = {
        Ahi + (size_t)m0 * K, Alo + (size_t)m0 * K,
        Bhi + (size_t)n0 * K, Blo + (size_t)n0 * K };

    const int NK = K / BK;              // 32

    auto issue_stage = [&](int ks, int st) {
        const int k0 = ks * BK;
        const uint32_t so = sb + st * STAGE_B;
        // A digit tiles: 64 rows x 8 chunks = 512 chunks each
#pragma unroll
        for (int mat = 0; mat < 2; mat++) {
            const __nv_bfloat16* bp = srcs[mat] + k0;
#pragma unroll
            for (int j = 0; j < 4; j++) {
                const int idx = j * 128 + tid;        // 0..511
                const int r = idx >> 3, ch = idx & 7;
                const uint32_t dst = so + mat * A_T_B + r * 128 + ((ch ^ (r & 7)) << 4);
                cp_async16(dst, bp + (size_t)r * K + ch * 8);
            }
        }
        // B digit tiles: 128 rows x 8 chunks = 1024 chunks each
#pragma unroll
        for (int mat = 0; mat < 2; mat++) {
            const __nv_bfloat16* bp = srcs[2 + mat] + k0;
#pragma unroll
            for (int j = 0; j < 8; j++) {
                const int idx = j * 128 + tid;        // 0..1023
                const int r = idx >> 3, ch = idx & 7;
                const uint32_t dst = so + 2 * A_T_B + mat * B_T_B
                                   + r * 128 + ((ch ^ (r & 7)) << 4);
                cp_async16(dst, bp + (size_t)r * K + ch * 8);
            }
        }
    };

    issue_stage(0, 0); cp_commit();
    issue_stage(1, 1); cp_commit();

    float acc[2][8][4];
#pragma unroll
    for (int i = 0; i < 2; i++)
#pragma unroll
        for (int j = 0; j < 8; j++)
#pragma unroll
            for (int k = 0; k < 4; k++) acc[i][j][k] = 0.f;

    const int rA = wm * 32 + ((lane >> 3) & 1) * 8 + (lane & 7);  // + mt*16
    const int cA = lane >> 4;
    const int rB = wn * 64 + (lane >> 4) * 8 + (lane & 7);        // + p*16
    const int cB = (lane >> 3) & 1;

    for (int ks = 0; ks < NK; ks++) {
        const int st = ks & 1;
        const uint32_t so = sb + st * STAGE_B;
        cp_wait1();
        __syncthreads();

        const uint32_t tAh = so;
        const uint32_t tAl = so + A_T_B;
        const uint32_t tBh = so + 2 * A_T_B;
        const uint32_t tBl = so + 2 * A_T_B + B_T_B;

#pragma unroll
        for (int kk = 0; kk < 4; kk++) {
            uint32_t ah[2][4], al[2][4], bh[16], bl[16];
#pragma unroll
            for (int mt = 0; mt < 2; mt++) {
                const int r = rA + mt * 16;
                const int ch = kk * 2 + cA;
                const uint32_t off = r * 128 + ((ch ^ (r & 7)) << 4);
                ldsm_x4(ah[mt], tAh + off);
                ldsm_x4(al[mt], tAl + off);
            }
#pragma unroll
            for (int p = 0; p < 4; p++) {
                const int r = rB + p * 16;
                const int ch = kk * 2 + cB;
                const uint32_t off = r * 128 + ((ch ^ (r & 7)) << 4);
                ldsm_x4(&bh[p * 4], tBh + off);
                ldsm_x4(&bl[p * 4], tBl + off);
            }
#pragma unroll
            for (int mt = 0; mt < 2; mt++)
#pragma unroll
                for (int nt = 0; nt < 8; nt++)
                    mma16816(acc[mt][nt], ah[mt], &bh[nt * 2]);
#pragma unroll
            for (int mt = 0; mt < 2; mt++)
#pragma unroll
                for (int nt = 0; nt < 8; nt++)
                    mma16816(acc[mt][nt], ah[mt], &bl[nt * 2]);
#pragma unroll
            for (int mt = 0; mt < 2; mt++)
#pragma unroll
                for (int nt = 0; nt < 8; nt++)
                    mma16816(acc[mt][nt], al[mt], &bh[nt * 2]);
        }
        __syncthreads();
        if (ks + 2 < NK) issue_stage(ks + 2, st);
        cp_commit();
    }

    const int cr  = lane >> 2;
    const int tig = lane & 3;
    const int cc  = tig * 2;

    if (FUSED == 0) {
#pragma unroll
        for (int mt = 0; mt < 2; mt++) {
            const int rowb = m0 + wm * 32 + mt * 16 + cr;
#pragma unroll
            for (int nt = 0; nt < 8; nt++) {
                const int col = n0 + wn * 64 + nt * 8 + cc;
                *(float2*)(C + (size_t)rowb * N + col) =
                    make_float2(acc[mt][nt][0], acc[mt][nt][1]);
                *(float2*)(C + (size_t)(rowb + 8) * N + col) =
                    make_float2(acc[mt][nt][2], acc[mt][nt][3]);
            }
        }
    } else {
        const int bx = blockIdx.x;
        const bool isQ = (bx < 16);
        const bool donorm = (bx < 20);
        __nv_bfloat16* Hi = isQ ? QHi : KVHi;
        __nv_bfloat16* Lo = isQ ? QLo : KVLo;
        const int ostride = isQ ? D : KVS;
        const int colbase = (isQ ? n0 : n0 - D) + wn * 64;
        const float* g = isQ ? gq : gk;
        const float qscl = isQ ? (0.125f * 1.44269504088896f) : 1.f;

#pragma unroll
        for (int mt = 0; mt < 2; mt++) {
#pragma unroll
            for (int half = 0; half < 2; half++) {
                const int k0 = half * 2;
                const int row = m0 + wm * 32 + mt * 16 + cr + half * 8;
                if (donorm) {
                    float ss = 0.f;
#pragma unroll
                    for (int nt = 0; nt < 8; nt++)
                        ss += acc[mt][nt][k0] * acc[mt][nt][k0]
                            + acc[mt][nt][k0 + 1] * acc[mt][nt][k0 + 1];
                    ss += __shfl_xor_sync(0xffffffffu, ss, 1);
                    ss += __shfl_xor_sync(0xffffffffu, ss, 2);
                    const float rr = rsqrtf(ss * (1.f / 64.f) + 1e-6f) * qscl;
#pragma unroll
                    for (int nt = 0; nt < 4; nt++) {
                        const int d0 = nt * 8 + cc;
                        const float x1a = acc[mt][nt][k0]     * rr * g[d0];
                        const float x1b = acc[mt][nt][k0 + 1] * rr * g[d0 + 1];
                        const float x2a = acc[mt][nt + 4][k0]     * rr * g[d0 + 32];
                        const float x2b = acc[mt][nt + 4][k0 + 1] * rr * g[d0 + 33];
                        const float ca = cosT[row * 32 + d0];
                        const float cb = cosT[row * 32 + d0 + 1];
                        const float sa = sinT[row * 32 + d0];
                        const float sbn = sinT[row * 32 + d0 + 1];
                        uint32_t h, l;
                        pack2(x1a * ca - x2a * sa, x1b * cb - x2b * sbn, h, l);
                        *(uint32_t*)(Hi + (size_t)row * ostride + colbase + d0) = h;
                        *(uint32_t*)(Lo + (size_t)row * ostride + colbase + d0) = l;
                        pack2(x1a * sa + x2a * ca, x1b * sbn + x2b * cb, h, l);
                        *(uint32_t*)(Hi + (size_t)row * ostride + colbase + d0 + 32) = h;
                        *(uint32_t*)(Lo + (size_t)row * ostride + colbase + d0 + 32) = l;
                    }
                } else {
#pragma unroll
                    for (int nt = 0; nt < 8; nt++) {
                        uint32_t h, l;
                        pack2(acc[mt][nt][k0], acc[mt][nt][k0 + 1], h, l);
                        const int col = colbase + nt * 8 + cc;
                        *(uint32_t*)(Hi + (size_t)row * ostride + col) = h;
                        *(uint32_t*)(Lo + (size_t)row * ostride + col) = l;
                    }
                }
            }
        }
    }
}

// ---------------------------------------------------------------------------
// Tensor-core causal GQA flash attention (unchanged from R15 — validated).
// ---------------------------------------------------------------------------
#define ATQ 64
#define ATK 64
#define AQL_OFF   8192
#define ASTG_OFF  16384
#define ASTG_SZ   32768
#define SMEM_ATTN (ASTG_OFF + 2 * ASTG_SZ + 128)   // ~80KB -> 2 CTAs/SM

__global__ __launch_bounds__(128, 2) void attn_tc(
    const __nv_bfloat16* __restrict__ Qhi, const __nv_bfloat16* __restrict__ Qlo,
    const __nv_bfloat16* __restrict__ KVhi, const __nv_bfloat16* __restrict__ KVlo,
    __nv_bfloat16* __restrict__ Ohi, __nv_bfloat16* __restrict__ Olo)
{
    extern __shared__ char smem_raw[];
    const uint32_t sb = (smem_u32(smem_raw) + 127) & ~127u;
    const int tid = threadIdx.x, wid = tid >> 5, lane = tid & 31;
    const int h = blockIdx.y, hk = h >> 2;
    const int qb = gridDim.x - 1 - blockIdx.x;
    const int q0 = qb * ATQ;
    const int g = lane >> 2, tig = lane & 3;

    const int ntile = (q0 + ATQ) / ATK;

    auto issue_kv = [&](int t, int st) {
        const int kb = t * ATK;
        const uint32_t so = sb + ASTG_OFF + st * ASTG_SZ;
        const __nv_bfloat16* bases[4] = {
            KVhi + (size_t)kb * KVS + hk * HD,
            KVlo + (size_t)kb * KVS + hk * HD,
            KVhi + (size_t)kb * KVS + DKV + hk * HD,
            KVlo + (size_t)kb * KVS + DKV + hk * HD };
#pragma unroll
        for (int mat = 0; mat < 4; mat++)
#pragma unroll
            for (int j = 0; j < 4; j++) {
                const int idx = j * 128 + tid;
                const int r = idx >> 3, ch = idx & 7;
                const uint32_t dst = so + mat * 8192 + r * 128 + ((ch ^ (r & 7)) << 4);
                cp_async16(dst, bases[mat] + (size_t)r * KVS + ch * 8);
            }
    };

    {
        const __nv_bfloat16* qsrc[2] = { Qhi + (size_t)q0 * D + h * HD,
                                         Qlo + (size_t)q0 * D + h * HD };
#pragma unroll
        for (int mat = 0; mat < 2; mat++)
#pragma unroll
            for (int j = 0; j < 4; j++) {
                const int idx = j * 128 + tid;
                const int r = idx >> 3, ch = idx & 7;
                const uint32_t dst = sb + mat * AQL_OFF + r * 128 + ((ch ^ (r & 7)) << 4);
                cp_async16(dst, qsrc[mat] + (size_t)r * D + ch * 8);
            }
    }
    cp_commit();
    issue_kv(0, 0); cp_commit();

    cp_wait1();
    __syncthreads();

    uint32_t qh[4][4], ql[4][4];
    {
        const int r = wid * 16 + (lane & 15);
        const int chb = lane >> 4;
#pragma unroll
        for (int kk = 0; kk < 4; kk++) {
            const int ch = kk * 2 + chb;
            const uint32_t off = r * 128 + ((ch ^ (r & 7)) << 4);
            ldsm_x4(qh[kk], sb + off);
            ldsm_x4(ql[kk], sb + AQL_OFF + off);
        }
    }

    float acc_o[8][4];
#pragma unroll
    for (int i = 0; i < 8; i++)
#pragma unroll
        for (int j = 0; j < 4; j++) acc_o[i][j] = 0.f;
    float m0 = -1e30f, m1 = -1e30f, l0 = 0.f, l1 = 0.f;

    const int row0 = q0 + wid * 16 + g;
    const int row1 = row0 + 8;

    for (int t = 0; t < ntile; t++) {
        if (t + 1 < ntile) { issue_kv(t + 1, (t + 1) & 1); cp_commit(); cp_wait1(); }
        else cp_wait0();
        __syncthreads();

        const uint32_t so = sb + ASTG_OFF + (t & 1) * ASTG_SZ;
        const int kb = t * ATK;

        float sc[8][4];
#pragma unroll
        for (int i = 0; i < 8; i++)
#pragma unroll
            for (int j = 0; j < 4; j++) sc[i][j] = 0.f;

        {
            const int rbase = ((lane >> 4) & 1) * 8 + (lane & 7);
            const int chb = (lane >> 3) & 1;
#pragma unroll
            for (int kk = 0; kk < 4; kk++)
#pragma unroll
                for (int i = 0; i < 4; i++) {
                    const int r = i * 16 + rbase;
                    const int ch = kk * 2 + chb;
                    const uint32_t off = r * 128 + ((ch ^ (r & 7)) << 4);
                    uint32_t bh[4], bl[4];
                    ldsm_x4(bh, so + off);
                    ldsm_x4(bl, so + 8192 + off);
                    mma16816(sc[2 * i],     qh[kk], &bh[0]);
                    mma16816(sc[2 * i],     qh[kk], &bl[0]);
                    mma16816(sc[2 * i],     ql[kk], &bh[0]);
                    mma16816(sc[2 * i + 1], qh[kk], &bh[2]);
                    mma16816(sc[2 * i + 1], qh[kk], &bl[2]);
                    mma16816(sc[2 * i + 1], ql[kk], &bh[2]);
                }
        }

        float nm0 = m0, nm1 = m1;
        if (kb >= q0) {
#pragma unroll
            for (int nt = 0; nt < 8; nt++) {
                const int colb = kb + nt * 8 + 2 * tig;
                if (colb     > row0) sc[nt][0] = -1e30f;
                if (colb + 1 > row0) sc[nt][1] = -1e30f;
                if (colb     > row1) sc[nt][2] = -1e30f;
                if (colb + 1 > row1) sc[nt][3] = -1e30f;
                nm0 = fmaxf(nm0, fmaxf(sc[nt][0], sc[nt][1]));
                nm1 = fmaxf(nm1, fmaxf(sc[nt][2], sc[nt][3]));
            }
        } else {
#pragma unroll
            for (int nt = 0; nt < 8; nt++) {
                nm0 = fmaxf(nm0, fmaxf(sc[nt][0], sc[nt][1]));
                nm1 = fmaxf(nm1, fmaxf(sc[nt][2], sc[nt][3]));
            }
        }
        nm0 = fmaxf(nm0, __shfl_xor_sync(0xffffffffu, nm0, 1));
        nm0 = fmaxf(nm0, __shfl_xor_sync(0xffffffffu, nm0, 2));
        nm1 = fmaxf(nm1, __shfl_xor_sync(0xffffffffu, nm1, 1));
        nm1 = fmaxf(nm1, __shfl_xor_sync(0xffffffffu, nm1, 2));
        const float c0 = ex2(m0 - nm0), c1 = ex2(m1 - nm1);
        m0 = nm0; m1 = nm1;
        l0 *= c0; l1 *= c1;
#pragma unroll
        for (int nt = 0; nt < 8; nt++) {
            acc_o[nt][0] *= c0; acc_o[nt][1] *= c0;
            acc_o[nt][2] *= c1; acc_o[nt][3] *= c1;
        }
#pragma unroll
        for (int nt = 0; nt < 8; nt++) {
            const float p0 = ex2(sc[nt][0] - m0), p1 = ex2(sc[nt][1] - m0);
            const float p2 = ex2(sc[nt][2] - m1), p3 = ex2(sc[nt][3] - m1);
            l0 += p0 + p1; l1 += p2 + p3;
            sc[nt][0] = p0; sc[nt][1] = p1; sc[nt][2] = p2; sc[nt][3] = p3;
        }

        {
            const int rbase = ((lane >> 3) & 1) * 8 + (lane & 7);
            const int chb = lane >> 4;
#pragma unroll
            for (int kc = 0; kc < 4; kc++) {
                uint32_t aH[4], aL[4];
                pack2(sc[2 * kc][0],     sc[2 * kc][1],     aH[0], aL[0]);
                pack2(sc[2 * kc][2],     sc[2 * kc][3],     aH[1], aL[1]);
                pack2(sc[2 * kc + 1][0], sc[2 * kc + 1][1], aH[2], aL[2]);
                pack2(sc[2 * kc + 1][2], sc[2 * kc + 1][3], aH[3], aL[3]);
                const int r = kc * 16 + rbase;
#pragma unroll
                for (int j = 0; j < 4; j++) {
                    const int ch = 2 * j + chb;
                    const uint32_t off = r * 128 + ((ch ^ (r & 7)) << 4);
                    uint32_t vh[4], vl[4];
                    ldsm_x4_t(vh, so + 16384 + off);
                    ldsm_x4_t(vl, so + 24576 + off);
                    mma16816(acc_o[2 * j],     aH, &vh[0]);
                    mma16816(acc_o[2 * j],     aH, &vl[0]);
                    mma16816(acc_o[2 * j],     aL, &vh[0]);
                    mma16816(acc_o[2 * j + 1], aH, &vh[2]);
                    mma16816(acc_o[2 * j + 1], aH, &vl[2]);
                    mma16816(acc_o[2 * j + 1], aL, &vh[2]);
                }
            }
        }
        __syncthreads();
    }

    l0 += __shfl_xor_sync(0xffffffffu, l0, 1);
    l0 += __shfl_xor_sync(0xffffffffu, l0, 2);
    l1 += __shfl_xor_sync(0xffffffffu, l1, 1);
    l1 += __shfl_xor_sync(0xffffffffu, l1, 2);
    const float i0 = 1.f / l0, i1 = 1.f / l1;
    const size_t b0 = (size_t)row0 * D + h * HD;
    const size_t b1 = (size_t)row1 * D + h * HD;
#pragma unroll
    for (int nt = 0; nt < 8; nt++) {
        const int co = nt * 8 + 2 * tig;
        uint32_t hi, lo;
        pack2(acc_o[nt][0] * i0, acc_o[nt][1] * i0, hi, lo);
        *(uint32_t*)(Ohi + b0 + co) = hi;
        *(uint32_t*)(Olo + b0 + co) = lo;
        pack2(acc_o[nt][2] * i1, acc_o[nt][3] * i1, hi, lo);
        *(uint32_t*)(Ohi + b1 + co) = hi;
        *(uint32_t*)(Olo + b1 + co) = lo;
    }
}

// ---------------------------------------------------------------------------
// Launcher — attention stays at capture slot #3; GEMMs now 2 CTAs/SM.
// ---------------------------------------------------------------------------
extern "C" void kernel_launch(void* const* d_in, const int* in_sizes, int n_in,
                              void* d_out, int out_size)
{
    const float* x    = (const float*)d_in[0];
    const float* cosT = (const float*)d_in[1];
    const float* sinT = (const float*)d_in[2];
    const float* gq   = (const float*)d_in[3];
    const float* gk   = (const float*)d_in[4];
    const float* Wq   = (const float*)d_in[5];
    const float* Wk   = (const float*)d_in[6];
    const float* Wv   = (const float*)d_in[7];
    const float* Wo   = (const float*)d_in[8];
    float* out = (float*)d_out;

    __nv_bfloat16 *Ahi, *Alo, *KVhi, *KVlo, *Ohi, *Olo;
    __nv_bfloat16 *WqkvTh, *WqkvTl, *WoTh, *WoTl;
    cudaGetSymbolAddress((void**)&Ahi,    g_Ahi);
    cudaGetSymbolAddress((void**)&Alo,    g_Alo);
    cudaGetSymbolAddress((void**)&KVhi,   g_KVhi);
    cudaGetSymbolAddress((void**)&KVlo,   g_KVlo);
    cudaGetSymbolAddress((void**)&Ohi,    g_Ohi);
    cudaGetSymbolAddress((void**)&Olo,    g_Olo);
    cudaGetSymbolAddress((void**)&WqkvTh, g_WqkvThi);
    cudaGetSymbolAddress((void**)&WqkvTl, g_WqkvTlo);
    cudaGetSymbolAddress((void**)&WoTh,   g_WoThi);
    cudaGetSymbolAddress((void**)&WoTl,   g_WoTlo);

    cudaFuncSetAttribute(gemm_mma<0>, cudaFuncAttributeMaxDynamicSharedMemorySize, SMEM_GEMM);
    cudaFuncSetAttribute(gemm_mma<1>, cudaFuncAttributeMaxDynamicSharedMemorySize, SMEM_GEMM);
    cudaFuncSetAttribute(attn_tc,     cudaFuncAttributeMaxDynamicSharedMemorySize, SMEM_ATTN);

    // #0: x split
    cvt_hilo<<<(S * D / 4 + 255) / 256, 256>>>(x, Ahi, Alo, S * D);
    // #1: merged Wq|Wk|Wv transpose+split
    cvt_hilo_T_qkv<<<dim3(DQKV / 32, D / 32), dim3(32, 8)>>>(Wq, Wk, Wv, WqkvTh, WqkvTl);

    // #2: fused QKV projection + RMSNorm + RoPE (+Q prescale) + hi/lo.
    //     768 CTAs, 2 per SM.
    gemm_mma<1><<<dim3(DQKV / 128, S / BM), 128, SMEM_GEMM>>>(
        Ahi, Alo, WqkvTh, WqkvTl, nullptr,
        Ohi, Olo, KVhi, KVlo, cosT, sinT, gq, gk, DQKV, D);

    // #3: attention (ncu capture slot). 1024 CTAs, 2 per SM.
    attn_tc<<<dim3(S / ATQ, NQ), 128, SMEM_ATTN>>>(Ohi, Olo, KVhi, KVlo, Ahi, Alo);

    // #4: Wo transpose+split
    cvt_hilo_T<<<dim3(D / 32, D / 32), dim3(32, 8)>>>(Wo, WoTh, WoTl, D, D);

    // #5: output projection (plain fp32 epilogue). 512 CTAs, 2 per SM.
    gemm_mma<0><<<dim3(D / 128, S / BM), 128, SMEM_GEMM>>>(
        Ahi, Alo, WoTh, WoTl, out,
        nullptr, nullptr, nullptr, nullptr, nullptr, nullptr, nullptr, nullptr, D, D);
}